// round 4
// baseline (speedup 1.0000x reference)
#include <cuda_runtime.h>
#include <cuda_fp16.h>
#include <math.h>

#define NB    4
#define NN    1000
#define NT    8
#define NF    64
#define NH    64
#define NHEAD 4
#define NE    16000
#define NG    32
#define GN    32000
#define BN    4000
#define TOTE  512000
#define NEG_SLOPE 0.2f

// -------------------- scratch ------------------------------------------------
__device__ __half2 g_hfeat16[GN * 128];   // h = in @ W, fp16 pairs [node][128]
__device__ float g_asrc[GN * 4];
__device__ float g_adst[GN * 4];
__device__ float g_gat1[GN * 64];
__device__ float g_gat2[GN * 64];
__device__ int   g_deg[GN];
__device__ int   g_offs[GN + 1];
__device__ int   g_cursor[GN];
__device__ int   g_srclist[TOTE];
// duplicated weights for f32x2: each scalar stored as (w,w)
__device__ float2 g_wih0D[64 * 192];
__device__ float2 g_whh0D[64 * 192];
__device__ float2 g_wih1D[64 * 192];
__device__ float2 g_whh1D[64 * 192];
__device__ float2 g_w1D[64 * 256];
__device__ float2 g_w2D[64 * 256];

// -------------------- fast math ----------------------------------------------
__device__ __forceinline__ float leaky(float x) { return fmaxf(x, NEG_SLOPE * x); }
__device__ __forceinline__ float fsig(float x) {
    float e = __expf(-fabsf(x));
    float r = __fdividef(1.f, 1.f + e);
    return x >= 0.f ? r : r * e;
}
__device__ __forceinline__ float ftanh(float x) {
    float e = __expf(-2.f * fabsf(x));
    float t = 1.f - __fdividef(2.f * e, 1.f + e);
    return x >= 0.f ? t : -t;
}
// packed fp32x2 fma (sm_100+)
__device__ __forceinline__ float2 ffma2(float2 a, float2 b, float2 c) {
    unsigned long long au = *(unsigned long long*)&a;
    unsigned long long bu = *(unsigned long long*)&b;
    unsigned long long cu = *(unsigned long long*)&c;
    unsigned long long du;
    asm("fma.rn.f32x2 %0, %1, %2, %3;" : "=l"(du) : "l"(au), "l"(bu), "l"(cu));
    return *(float2*)&du;
}

// -------------------- init + weight prep ---------------------------------------
__global__ void init_kernel() {
    int i = blockIdx.x * blockDim.x + threadIdx.x;
    if (i < GN) g_deg[i] = 0;
}

__global__ void wtrans_kernel(const float* __restrict__ Whh0,
                              const float* __restrict__ Wih1,
                              const float* __restrict__ Whh1,
                              const float* __restrict__ Wih0,
                              const float* __restrict__ W1,
                              const float* __restrict__ W2) {
    int i = blockIdx.x * blockDim.x + threadIdx.x;
    if (i < 12288) {
        int j = i / 64, k = i % 64;     // weight [j][k] -> dup-transposed [k][j]
        g_wih0D[k * 192 + j] = make_float2(Wih0[i], Wih0[i]);
        g_whh0D[k * 192 + j] = make_float2(Whh0[i], Whh0[i]);
        g_wih1D[k * 192 + j] = make_float2(Wih1[i], Wih1[i]);
        g_whh1D[k * 192 + j] = make_float2(Whh1[i], Whh1[i]);
    }
    if (i < 16384) {                    // W1/W2 already [k][j]
        g_w1D[i] = make_float2(W1[i], W1[i]);
        g_w2D[i] = make_float2(W2[i], W2[i]);
    }
}

// -------------------- CSR build ------------------------------------------------
__global__ void hist_kernel(const int* __restrict__ ei) {
    for (int e = blockIdx.x * blockDim.x + threadIdx.x; e < TOTE;
         e += gridDim.x * blockDim.x) {
        int g = e / NE, el = e % NE;
        int dst = ei[(g * 2 + 1) * NE + el];
        atomicAdd(&g_deg[g * NN + dst], 1);
    }
}

// per-graph scan: 32 blocks x 1024 threads, one node per thread.
__global__ void scan_kernel() {
    __shared__ int wsum[32];
    int g = blockIdx.x;
    int tid = threadIdx.x, lane = tid & 31, wid = tid >> 5;
    int d = (tid < NN) ? g_deg[g * NN + tid] : 0;
    int s = d;
#pragma unroll
    for (int o = 1; o < 32; o <<= 1) {
        int v = __shfl_up_sync(0xffffffffu, s, o);
        if (lane >= o) s += v;
    }
    if (lane == 31) wsum[wid] = s;
    __syncthreads();
    if (wid == 0) {
        int v = wsum[lane];
#pragma unroll
        for (int o = 1; o < 32; o <<= 1) {
            int u = __shfl_up_sync(0xffffffffu, v, o);
            if (lane >= o) v += u;
        }
        wsum[lane] = v;
    }
    __syncthreads();
    int incl = s + (wid > 0 ? wsum[wid - 1] : 0);
    int excl = incl - d;
    if (tid < NN) {
        int node = g * NN + tid;
        int off = g * NE + excl;
        g_offs[node] = off;
        g_cursor[node] = off;
    }
    if (g == 0 && tid == 0) g_offs[GN] = TOTE;
}

__global__ void scatter_kernel(const int* __restrict__ ei) {
    for (int e = blockIdx.x * blockDim.x + threadIdx.x; e < TOTE;
         e += gridDim.x * blockDim.x) {
        int g = e / NE, el = e % NE;
        int src = ei[(g * 2 + 0) * NE + el];
        int dst = ei[(g * 2 + 1) * NE + el];
        int pos = atomicAdd(&g_cursor[g * NN + dst], 1);
        g_srclist[pos] = src;
    }
}

// -------------------- GAT prologue (f32x2) + attention scalars ------------------
// 256 threads: cq = t&63 -> 4 cols, rq = t>>6 -> 16 rows. hfeat stored fp16.
__global__ __launch_bounds__(256)
void prologue_kernel(const float* __restrict__ in,
                     const float* __restrict__ att_src, const float* __restrict__ att_dst,
                     int mode) {
    __shared__ float xsT[64 * 68];   // [k][r] padded
    int t = threadIdx.x;
    int cq = t & 63, rq = t >> 6;
    int lane = t & 31;
    int nodebase = blockIdx.x * 64;

    for (int linear = t; linear < 4096; linear += 256) {
        int r = linear >> 6, k = linear & 63;
        int node = nodebase + r;
        float v;
        if (mode == 0) {
            int gg = node / NN, n = node % NN;
            int b = gg >> 3, tt = gg & 7;
            v = in[((b * NN + n) * NT + tt) * NF + k];
        } else {
            v = g_gat1[node * 64 + k];
        }
        xsT[k * 68 + r] = v;
    }
    __syncthreads();

    const float4* WD = (const float4*)(mode == 0 ? g_w1D : g_w2D);
    float2 acc[8][4];
#pragma unroll
    for (int p = 0; p < 8; p++)
#pragma unroll
        for (int c = 0; c < 4; c++) acc[p][c] = make_float2(0.f, 0.f);

    int rbase = rq * 16;
    for (int k = 0; k < 64; k++) {
        float4 wa = __ldg(&WD[k * 128 + cq * 2]);      // (w0,w0,w1,w1)
        float4 wb = __ldg(&WD[k * 128 + cq * 2 + 1]);  // (w2,w2,w3,w3)
        float2 w0 = make_float2(wa.x, wa.y);
        float2 w1 = make_float2(wa.z, wa.w);
        float2 w2 = make_float2(wb.x, wb.y);
        float2 w3 = make_float2(wb.z, wb.w);
        const float* xk = &xsT[k * 68 + rbase];
#pragma unroll
        for (int q = 0; q < 4; q++) {
            float4 xq = *(const float4*)&xk[q * 4];
            float2 pa = make_float2(xq.x, xq.y);
            float2 pb = make_float2(xq.z, xq.w);
            acc[q * 2 + 0][0] = ffma2(pa, w0, acc[q * 2 + 0][0]);
            acc[q * 2 + 0][1] = ffma2(pa, w1, acc[q * 2 + 0][1]);
            acc[q * 2 + 0][2] = ffma2(pa, w2, acc[q * 2 + 0][2]);
            acc[q * 2 + 0][3] = ffma2(pa, w3, acc[q * 2 + 0][3]);
            acc[q * 2 + 1][0] = ffma2(pb, w0, acc[q * 2 + 1][0]);
            acc[q * 2 + 1][1] = ffma2(pb, w1, acc[q * 2 + 1][1]);
            acc[q * 2 + 1][2] = ffma2(pb, w2, acc[q * 2 + 1][2]);
            acc[q * 2 + 1][3] = ffma2(pb, w3, acc[q * 2 + 1][3]);
        }
    }

    float4 as4 = __ldg((const float4*)&att_src[cq * 4]);
    float4 ad4 = __ldg((const float4*)&att_dst[cq * 4]);
    int hd = cq >> 4;

#pragma unroll
    for (int i = 0; i < 16; i++) {
        int p = i >> 1, e = i & 1;
        float c0 = e ? acc[p][0].y : acc[p][0].x;
        float c1 = e ? acc[p][1].y : acc[p][1].x;
        float c2 = e ? acc[p][2].y : acc[p][2].x;
        float c3 = e ? acc[p][3].y : acc[p][3].x;
        int node = nodebase + rbase + i;

        __half2 h0 = __floats2half2_rn(c0, c1);
        __half2 h1 = __floats2half2_rn(c2, c3);
        uint2 u;
        u.x = *(unsigned*)&h0;
        u.y = *(unsigned*)&h1;
        *(uint2*)&g_hfeat16[node * 128 + cq * 2] = u;

        float ps = c0 * as4.x + c1 * as4.y + c2 * as4.z + c3 * as4.w;
        float pd = c0 * ad4.x + c1 * ad4.y + c2 * ad4.z + c3 * ad4.w;
#pragma unroll
        for (int o = 8; o; o >>= 1) {
            ps += __shfl_xor_sync(0xffffffffu, ps, o);
            pd += __shfl_xor_sync(0xffffffffu, pd, o);
        }
        if ((lane & 15) == 0) {
            g_asrc[node * 4 + hd] = ps;
            g_adst[node * 4 + hd] = pd;
        }
    }
}

// -------------------- GAT aggregation (fp16 gather) ------------------------------
__global__ __launch_bounds__(128)
void aggregate_kernel(const float* __restrict__ bias, int relu_flag, int which) {
    __shared__ float4 sm_alpha[128];
    __shared__ int    sm_src[128];
    __shared__ float4 sm_sinv;
    __shared__ float  sred[256];

    int node = blockIdx.x;
    int g = node / NN;
    int gbase = g * NN;
    int tid = threadIdx.x;
    int off = g_offs[node];
    int deg = g_offs[node + 1] - off;

    float4 ad4 = *(const float4*)&g_adst[node * 4];
    float4 asn = *(const float4*)&g_asrc[node * 4];

    if (tid < 32) {
        float4 s;
        s.x = s.y = s.z = s.w = 0.f;
        for (int j = tid; j < deg; j += 32) {
            int src = g_srclist[off + j];
            float4 as = __ldg((const float4*)&g_asrc[(gbase + src) * 4]);
            s.x += __expf(leaky(as.x + ad4.x));
            s.y += __expf(leaky(as.y + ad4.y));
            s.z += __expf(leaky(as.z + ad4.z));
            s.w += __expf(leaky(as.w + ad4.w));
        }
        if (tid == 0) {
            s.x += __expf(leaky(asn.x + ad4.x));
            s.y += __expf(leaky(asn.y + ad4.y));
            s.z += __expf(leaky(asn.z + ad4.z));
            s.w += __expf(leaky(asn.w + ad4.w));
        }
#pragma unroll
        for (int o = 16; o; o >>= 1) {
            s.x += __shfl_xor_sync(0xffffffffu, s.x, o);
            s.y += __shfl_xor_sync(0xffffffffu, s.y, o);
            s.z += __shfl_xor_sync(0xffffffffu, s.z, o);
            s.w += __shfl_xor_sync(0xffffffffu, s.w, o);
        }
        if (tid == 0) {
            float4 inv;
            inv.x = __fdividef(1.f, s.x); inv.y = __fdividef(1.f, s.y);
            inv.z = __fdividef(1.f, s.z); inv.w = __fdividef(1.f, s.w);
            sm_sinv = inv;
        }
    }
    __syncthreads();
    float4 sinv = sm_sinv;

    int head = tid >> 5;
    int pi = tid & 31;

    float sinv_h = ((const float*)&sinv)[head];
    float ash = ((const float*)&asn)[head];
    float adh = ((const float*)&ad4)[head];
    float a_self = __expf(leaky(ash + adh)) * sinv_h;
    float2 hv = __half22float2(g_hfeat16[node * 128 + head * 32 + pi]);
    float accx = a_self * hv.x;
    float accy = a_self * hv.y;

    for (int base = 0; base < deg; base += 128) {
        int cnt = min(128, deg - base);
        __syncthreads();
        if (tid < cnt) {
            int src = g_srclist[off + base + tid];
            sm_src[tid] = gbase + src;
            float4 as = __ldg((const float4*)&g_asrc[(gbase + src) * 4]);
            float4 al;
            al.x = __expf(leaky(as.x + ad4.x)) * sinv.x;
            al.y = __expf(leaky(as.y + ad4.y)) * sinv.y;
            al.z = __expf(leaky(as.z + ad4.z)) * sinv.z;
            al.w = __expf(leaky(as.w + ad4.w)) * sinv.w;
            sm_alpha[tid] = al;
        }
        __syncthreads();
        const float* alp = (const float*)sm_alpha;
#pragma unroll 4
        for (int j = 0; j < cnt; j++) {
            int sg = sm_src[j];
            float a = alp[j * 4 + head];
            float2 f = __half22float2(__ldg(&g_hfeat16[sg * 128 + head * 32 + pi]));
            accx += a * f.x;
            accy += a * f.y;
        }
    }

    sred[tid * 2] = accx;
    sred[tid * 2 + 1] = accy;
    __syncthreads();
    if (tid < 32) {
        float vx = sred[tid * 2] + sred[64 + tid * 2] + sred[128 + tid * 2] + sred[192 + tid * 2];
        float vy = sred[tid * 2 + 1] + sred[64 + tid * 2 + 1] + sred[128 + tid * 2 + 1] + sred[192 + tid * 2 + 1];
        float2 b = *(const float2*)&bias[tid * 2];
        vx = vx * 0.25f + b.x;
        vy = vy * 0.25f + b.y;
        if (relu_flag) { vx = fmaxf(vx, 0.f); vy = fmaxf(vy, 0.f); }
        float2 o = make_float2(vx, vy);
        if (which == 0) *(float2*)&g_gat1[node * 64 + tid * 2] = o;
        else            *(float2*)&g_gat2[node * 64 + tid * 2] = o;
    }
}

// -------------------- fused GRU (all 8 timesteps) + head MLP ---------------------
// 250 blocks x 192 threads; block owns 16 rows for the whole sequence.
// cq = tid%48 -> 4 cols of 192; rq = tid/48 -> 4 rows (2 f32x2 pairs).
__device__ __forceinline__ void gru_layer(
    const float* __restrict__ xT, const float* __restrict__ hT,
    const float4* __restrict__ WiD, const float4* __restrict__ WhD,
    float4 bi, float4 bh,
    float* __restrict__ st, float* __restrict__ st2,
    int cq, int rb, int cbase, int gate)
{
    float2 gi[2][4], gh[2][4];
#pragma unroll
    for (int p = 0; p < 2; p++)
#pragma unroll
        for (int c = 0; c < 4; c++) {
            gi[p][c] = make_float2(0.f, 0.f);
            gh[p][c] = make_float2(0.f, 0.f);
        }
    for (int k = 0; k < 64; k++) {
        float4 wia = __ldg(&WiD[k * 96 + cq * 2]);
        float4 wib = __ldg(&WiD[k * 96 + cq * 2 + 1]);
        float4 wha = __ldg(&WhD[k * 96 + cq * 2]);
        float4 whb = __ldg(&WhD[k * 96 + cq * 2 + 1]);
        float4 xq = *(const float4*)&xT[k * 20 + rb];
        float4 hq = *(const float4*)&hT[k * 20 + rb];
        float2 xa = make_float2(xq.x, xq.y), xb = make_float2(xq.z, xq.w);
        float2 ha = make_float2(hq.x, hq.y), hb = make_float2(hq.z, hq.w);
        float2 wi0 = make_float2(wia.x, wia.y), wi1 = make_float2(wia.z, wia.w);
        float2 wi2 = make_float2(wib.x, wib.y), wi3 = make_float2(wib.z, wib.w);
        float2 wh0 = make_float2(wha.x, wha.y), wh1 = make_float2(wha.z, wha.w);
        float2 wh2 = make_float2(whb.x, whb.y), wh3 = make_float2(whb.z, whb.w);
        gi[0][0] = ffma2(xa, wi0, gi[0][0]); gi[0][1] = ffma2(xa, wi1, gi[0][1]);
        gi[0][2] = ffma2(xa, wi2, gi[0][2]); gi[0][3] = ffma2(xa, wi3, gi[0][3]);
        gi[1][0] = ffma2(xb, wi0, gi[1][0]); gi[1][1] = ffma2(xb, wi1, gi[1][1]);
        gi[1][2] = ffma2(xb, wi2, gi[1][2]); gi[1][3] = ffma2(xb, wi3, gi[1][3]);
        gh[0][0] = ffma2(ha, wh0, gh[0][0]); gh[0][1] = ffma2(ha, wh1, gh[0][1]);
        gh[0][2] = ffma2(ha, wh2, gh[0][2]); gh[0][3] = ffma2(ha, wh3, gh[0][3]);
        gh[1][0] = ffma2(hb, wh0, gh[1][0]); gh[1][1] = ffma2(hb, wh1, gh[1][1]);
        gh[1][2] = ffma2(hb, wh2, gh[1][2]); gh[1][3] = ffma2(hb, wh3, gh[1][3]);
    }
#pragma unroll
    for (int p = 0; p < 2; p++) {
#pragma unroll
        for (int e = 0; e < 2; e++) {
            int r = rb + p * 2 + e;
            float g0 = e ? gi[p][0].y : gi[p][0].x;
            float g1 = e ? gi[p][1].y : gi[p][1].x;
            float g2 = e ? gi[p][2].y : gi[p][2].x;
            float g3 = e ? gi[p][3].y : gi[p][3].x;
            float h0 = e ? gh[p][0].y : gh[p][0].x;
            float h1 = e ? gh[p][1].y : gh[p][1].x;
            float h2 = e ? gh[p][2].y : gh[p][2].x;
            float h3 = e ? gh[p][3].y : gh[p][3].x;
            float4 giv = make_float4(g0 + bi.x, g1 + bi.y, g2 + bi.z, g3 + bi.w);
            float4 ghv = make_float4(h0 + bh.x, h1 + bh.y, h2 + bh.z, h3 + bh.w);
            if (gate < 2) {
                *(float4*)&st[r * 196 + cbase] =
                    make_float4(giv.x + ghv.x, giv.y + ghv.y, giv.z + ghv.z, giv.w + ghv.w);
            } else {
                *(float4*)&st[r * 196 + cbase] = giv;
                *(float4*)&st2[r * 64 + (cbase - 128)] = ghv;
            }
        }
    }
}

__global__ __launch_bounds__(192)
void gru_fused_kernel(const float* __restrict__ bih0, const float* __restrict__ bhh0,
                      const float* __restrict__ bih1, const float* __restrict__ bhh1,
                      const float* __restrict__ pW1, const float* __restrict__ pb1,
                      const float* __restrict__ pW2, const float* __restrict__ pb2,
                      float* __restrict__ out) {
    const int R = 16;
    __shared__ float xsT[64 * 20];
    __shared__ float h1T[64 * 20];
    __shared__ float h2T[64 * 20];
    __shared__ float st[R * 196];
    __shared__ float st2[R * 64];

    int tid = threadIdx.x;
    int cq = tid % 48, rq = tid / 48;
    int rowbase = blockIdx.x * R;
    int cbase = cq * 4;
    int gate = cq >> 4;
    int rb = rq * 4;

    for (int idx = tid; idx < 64 * 20; idx += 192) {
        h1T[idx] = 0.f;
        h2T[idx] = 0.f;
    }

    float4 vbih0 = __ldg((const float4*)&bih0[cbase]);
    float4 vbhh0 = __ldg((const float4*)&bhh0[cbase]);
    float4 vbih1 = __ldg((const float4*)&bih1[cbase]);
    float4 vbhh1 = __ldg((const float4*)&bhh1[cbase]);

    const float4* Wi0 = (const float4*)g_wih0D;
    const float4* Wh0 = (const float4*)g_whh0D;
    const float4* Wi1 = (const float4*)g_wih1D;
    const float4* Wh1 = (const float4*)g_whh1D;

    for (int t = 0; t < NT; t++) {
        __syncthreads();
        for (int idx = tid; idx < R * 64; idx += 192) {
            int r = idx >> 6, k = idx & 63;
            int row = rowbase + r;
            int b = row / NN, n = row % NN;
            xsT[k * 20 + r] = g_gat2[((b * NT + t) * NN + n) * 64 + k];
        }
        __syncthreads();

        // layer 1
        gru_layer(xsT, h1T, Wi0, Wh0, vbih0, vbhh0, st, st2, cq, rb, cbase, gate);
        __syncthreads();
        for (int idx = tid; idx < R * 64; idx += 192) {
            int r = idx >> 6, c = idx & 63;
            float rg = fsig(st[r * 196 + c]);
            float zg = fsig(st[r * 196 + 64 + c]);
            float nv = ftanh(st[r * 196 + 128 + c] + rg * st2[r * 64 + c]);
            float h1o = h1T[c * 20 + r];
            h1T[c * 20 + r] = (1.f - zg) * nv + zg * h1o;
        }
        __syncthreads();

        // layer 2
        gru_layer(h1T, h2T, Wi1, Wh1, vbih1, vbhh1, st, st2, cq, rb, cbase, gate);
        __syncthreads();
        for (int idx = tid; idx < R * 64; idx += 192) {
            int r = idx >> 6, c = idx & 63;
            float rg = fsig(st[r * 196 + c]);
            float zg = fsig(st[r * 196 + 64 + c]);
            float nv = ftanh(st[r * 196 + 128 + c] + rg * st2[r * 64 + c]);
            float h2o = h2T[c * 20 + r];
            h2T[c * 20 + r] = (1.f - zg) * nv + zg * h2o;
        }
    }
    __syncthreads();

    // head MLP: mid = relu(h2 @ pW1 + pb1) stored in st (stride 68)
    if (tid < 128) {
        int j = tid & 63, rh = tid >> 6;
        for (int r = rh * 8; r < rh * 8 + 8; r++) {
            float a = __ldg(&pb1[j]);
            for (int k = 0; k < 64; k++) a += h2T[k * 20 + r] * __ldg(&pW1[k * 64 + j]);
            st[r * 68 + j] = fmaxf(a, 0.f);
        }
    }
    __syncthreads();
    if (tid < 160) {
        int r = tid / 10, o = tid % 10;
        float a = __ldg(&pb2[o]);
        for (int k = 0; k < 64; k++) a += st[r * 68 + k] * __ldg(&pW2[k * 10 + o]);
        out[(rowbase + r) * 10 + o] = a;
    }
}

// -------------------- launch ------------------------------------------------------
extern "C" void kernel_launch(void* const* d_in, const int* in_sizes, int n_in,
                              void* d_out, int out_size) {
    const float* x    = (const float*)d_in[0];
    const int*   ei   = (const int*)  d_in[1];
    const float* W1   = (const float*)d_in[3];
    const float* as1  = (const float*)d_in[4];
    const float* ad1  = (const float*)d_in[5];
    const float* b1   = (const float*)d_in[6];
    const float* W2   = (const float*)d_in[7];
    const float* as2  = (const float*)d_in[8];
    const float* ad2  = (const float*)d_in[9];
    const float* b2   = (const float*)d_in[10];
    const float* Wih0 = (const float*)d_in[13];
    const float* Whh0 = (const float*)d_in[14];
    const float* bih0 = (const float*)d_in[15];
    const float* bhh0 = (const float*)d_in[16];
    const float* Wih1 = (const float*)d_in[17];
    const float* Whh1 = (const float*)d_in[18];
    const float* bih1 = (const float*)d_in[19];
    const float* bhh1 = (const float*)d_in[20];
    const float* pW1  = (const float*)d_in[21];
    const float* pb1  = (const float*)d_in[22];
    const float* pW2  = (const float*)d_in[23];
    const float* pb2  = (const float*)d_in[24];
    float* out = (float*)d_out;

    init_kernel<<<125, 256>>>();
    wtrans_kernel<<<64, 256>>>(Whh0, Wih1, Whh1, Wih0, W1, W2);
    hist_kernel<<<2000, 256>>>(ei);
    scan_kernel<<<32, 1024>>>();
    scatter_kernel<<<2000, 256>>>(ei);

    // GAT layer 1
    prologue_kernel<<<GN / 64, 256>>>(x, as1, ad1, 0);
    aggregate_kernel<<<GN, 128>>>(b1, 1, 0);

    // GAT layer 2
    prologue_kernel<<<GN / 64, 256>>>(nullptr, as2, ad2, 1);
    aggregate_kernel<<<GN, 128>>>(b2, 0, 1);

    // GRU (all timesteps) + head
    gru_fused_kernel<<<BN / 16, 192>>>(bih0, bhh0, bih1, bhh1, pW1, pb1, pW2, pb2, out);
}

// round 5
// speedup vs baseline: 1.3154x; 1.3154x over previous
#include <cuda_runtime.h>
#include <cuda_fp16.h>
#include <math.h>

#define NB    4
#define NN    1000
#define NT    8
#define NF    64
#define NH    64
#define NHEAD 4
#define NE    16000
#define NG    32
#define GN    32000
#define BN    4000
#define TOTE  512000
#define NEG_SLOPE 0.2f

// -------------------- scratch ------------------------------------------------
__device__ __half2 g_hfeat16[GN * 128];   // h = in @ W, fp16 pairs [node][128]
__device__ float g_asrc[GN * 4];
__device__ float g_adst[GN * 4];
__device__ float g_gat1[GN * 64];
__device__ float g_gat2[GN * 64];
__device__ float g_gi[NT * BN * 192];
__device__ float g_h1[BN * 64];
__device__ float g_h2[BN * 64];
__device__ int   g_deg[GN];
__device__ int   g_offs[GN + 1];
__device__ int   g_cursor[GN];
__device__ int   g_srclist[TOTE];
// transposed weights [k][j]
__device__ float g_whh0T[64 * 192];
__device__ float g_wih1T[64 * 192];
__device__ float g_whh1T[64 * 192];
__device__ float g_wih0T[64 * 192];

// -------------------- fast math ----------------------------------------------
__device__ __forceinline__ float leaky(float x) { return fmaxf(x, NEG_SLOPE * x); }
__device__ __forceinline__ float fsig(float x) {
    float e = __expf(-fabsf(x));
    float r = __fdividef(1.f, 1.f + e);
    return x >= 0.f ? r : r * e;
}
__device__ __forceinline__ float ftanh(float x) {
    float e = __expf(-2.f * fabsf(x));
    float t = 1.f - __fdividef(2.f * e, 1.f + e);
    return x >= 0.f ? t : -t;
}

// -------------------- init ----------------------------------------------------
__global__ void init_kernel() {
    int total = GN + BN * 64 * 2;
    for (int i = blockIdx.x * blockDim.x + threadIdx.x; i < total;
         i += gridDim.x * blockDim.x) {
        if (i < GN) g_deg[i] = 0;
        else if (i < GN + BN * 64) g_h1[i - GN] = 0.f;
        else g_h2[i - GN - BN * 64] = 0.f;
    }
}

__global__ void wtrans_kernel(const float* __restrict__ Whh0,
                              const float* __restrict__ Wih1,
                              const float* __restrict__ Whh1,
                              const float* __restrict__ Wih0) {
    int i = blockIdx.x * blockDim.x + threadIdx.x;
    if (i >= 12288) return;
    int j = i / 64, k = i % 64;
    g_whh0T[k * 192 + j] = Whh0[i];
    g_wih1T[k * 192 + j] = Wih1[i];
    g_whh1T[k * 192 + j] = Whh1[i];
    g_wih0T[k * 192 + j] = Wih0[i];
}

// -------------------- CSR build ------------------------------------------------
__global__ void hist_kernel(const int* __restrict__ ei) {
    for (int e = blockIdx.x * blockDim.x + threadIdx.x; e < TOTE;
         e += gridDim.x * blockDim.x) {
        int g = e / NE, el = e % NE;
        int dst = ei[(g * 2 + 1) * NE + el];
        atomicAdd(&g_deg[g * NN + dst], 1);
    }
}

// per-graph scan: 32 blocks x 1024 threads, one node per thread.
__global__ void scan_kernel() {
    __shared__ int wsum[32];
    int g = blockIdx.x;
    int tid = threadIdx.x, lane = tid & 31, wid = tid >> 5;
    int d = (tid < NN) ? g_deg[g * NN + tid] : 0;
    int s = d;
#pragma unroll
    for (int o = 1; o < 32; o <<= 1) {
        int v = __shfl_up_sync(0xffffffffu, s, o);
        if (lane >= o) s += v;
    }
    if (lane == 31) wsum[wid] = s;
    __syncthreads();
    if (wid == 0) {
        int v = wsum[lane];
#pragma unroll
        for (int o = 1; o < 32; o <<= 1) {
            int u = __shfl_up_sync(0xffffffffu, v, o);
            if (lane >= o) v += u;
        }
        wsum[lane] = v;
    }
    __syncthreads();
    int incl = s + (wid > 0 ? wsum[wid - 1] : 0);
    int excl = incl - d;
    if (tid < NN) {
        int node = g * NN + tid;
        int off = g * NE + excl;
        g_offs[node] = off;
        g_cursor[node] = off;
    }
    if (g == 0 && tid == 0) g_offs[GN] = TOTE;
}

__global__ void scatter_kernel(const int* __restrict__ ei) {
    for (int e = blockIdx.x * blockDim.x + threadIdx.x; e < TOTE;
         e += gridDim.x * blockDim.x) {
        int g = e / NE, el = e % NE;
        int src = ei[(g * 2 + 0) * NE + el];
        int dst = ei[(g * 2 + 1) * NE + el];
        int pos = atomicAdd(&g_cursor[g * NN + dst], 1);
        g_srclist[pos] = src;
    }
}

// -------------------- GAT prologue + attention scalars -------------------------
// Block: 64 nodes x 256 cols. 256 threads; cq = t&63 -> 4 cols, rq = t>>6 -> 16 rows.
// mode 0: read input x; mode 1: read g_gat1 (device global). hfeat stored fp16.
__global__ __launch_bounds__(256)
void prologue_kernel(const float* __restrict__ in, const float* __restrict__ W,
                     const float* __restrict__ att_src, const float* __restrict__ att_dst,
                     int mode) {
    __shared__ float xsT[64 * 68];   // [k][r], padded
    int t = threadIdx.x;
    int cq = t & 63, rq = t >> 6;
    int lane = t & 31;
    int nodebase = blockIdx.x * 64;

    for (int linear = t; linear < 4096; linear += 256) {
        int r = linear >> 6, k = linear & 63;
        int node = nodebase + r;
        float v;
        if (mode == 0) {
            int gg = node / NN, n = node % NN;
            int b = gg >> 3, tt = gg & 7;
            v = in[((b * NN + n) * NT + tt) * NF + k];
        } else {
            v = g_gat1[node * 64 + k];
        }
        xsT[k * 68 + r] = v;
    }
    __syncthreads();

    const float4* Wv = (const float4*)W;
    float4 acc[16];
#pragma unroll
    for (int i = 0; i < 16; i++) acc[i] = make_float4(0.f, 0.f, 0.f, 0.f);

    int rbase = rq * 16;
    for (int k = 0; k < 64; k++) {
        float4 w = __ldg(&Wv[k * 64 + cq]);
        const float* xk = &xsT[k * 68 + rbase];
#pragma unroll
        for (int i = 0; i < 4; i++) {
            float4 xv = *(const float4*)&xk[i * 4];
            acc[i * 4 + 0].x += xv.x * w.x; acc[i * 4 + 0].y += xv.x * w.y;
            acc[i * 4 + 0].z += xv.x * w.z; acc[i * 4 + 0].w += xv.x * w.w;
            acc[i * 4 + 1].x += xv.y * w.x; acc[i * 4 + 1].y += xv.y * w.y;
            acc[i * 4 + 1].z += xv.y * w.z; acc[i * 4 + 1].w += xv.y * w.w;
            acc[i * 4 + 2].x += xv.z * w.x; acc[i * 4 + 2].y += xv.z * w.y;
            acc[i * 4 + 2].z += xv.z * w.z; acc[i * 4 + 2].w += xv.z * w.w;
            acc[i * 4 + 3].x += xv.w * w.x; acc[i * 4 + 3].y += xv.w * w.y;
            acc[i * 4 + 3].z += xv.w * w.z; acc[i * 4 + 3].w += xv.w * w.w;
        }
    }

    float4 as4 = __ldg((const float4*)&att_src[cq * 4]);
    float4 ad4 = __ldg((const float4*)&att_dst[cq * 4]);
    int hd = cq >> 4;

#pragma unroll
    for (int i = 0; i < 16; i++) {
        int node = nodebase + rbase + i;
        float4 a = acc[i];

        __half2 h0 = __floats2half2_rn(a.x, a.y);
        __half2 h1 = __floats2half2_rn(a.z, a.w);
        uint2 u;
        u.x = *(unsigned*)&h0;
        u.y = *(unsigned*)&h1;
        *(uint2*)&g_hfeat16[node * 128 + cq * 2] = u;

        float ps = a.x * as4.x + a.y * as4.y + a.z * as4.z + a.w * as4.w;
        float pd = a.x * ad4.x + a.y * ad4.y + a.z * ad4.z + a.w * ad4.w;
#pragma unroll
        for (int o = 8; o; o >>= 1) {
            ps += __shfl_xor_sync(0xffffffffu, ps, o);
            pd += __shfl_xor_sync(0xffffffffu, pd, o);
        }
        if ((lane & 15) == 0) {
            g_asrc[node * 4 + hd] = ps;
            g_adst[node * 4 + hd] = pd;
        }
    }
}

// -------------------- GAT aggregation (fp16 gather) ------------------------------
__global__ __launch_bounds__(128)
void aggregate_kernel(const float* __restrict__ bias, int relu_flag, int which) {
    __shared__ float4 sm_alpha[128];
    __shared__ int    sm_src[128];
    __shared__ float4 sm_sinv;
    __shared__ float  sred[256];

    int node = blockIdx.x;
    int g = node / NN;
    int gbase = g * NN;
    int tid = threadIdx.x;
    int off = g_offs[node];
    int deg = g_offs[node + 1] - off;

    float4 ad4 = *(const float4*)&g_adst[node * 4];
    float4 asn = *(const float4*)&g_asrc[node * 4];

    if (tid < 32) {
        float4 s;
        s.x = s.y = s.z = s.w = 0.f;
        for (int j = tid; j < deg; j += 32) {
            int src = g_srclist[off + j];
            float4 as = __ldg((const float4*)&g_asrc[(gbase + src) * 4]);
            s.x += __expf(leaky(as.x + ad4.x));
            s.y += __expf(leaky(as.y + ad4.y));
            s.z += __expf(leaky(as.z + ad4.z));
            s.w += __expf(leaky(as.w + ad4.w));
        }
        if (tid == 0) {
            s.x += __expf(leaky(asn.x + ad4.x));
            s.y += __expf(leaky(asn.y + ad4.y));
            s.z += __expf(leaky(asn.z + ad4.z));
            s.w += __expf(leaky(asn.w + ad4.w));
        }
#pragma unroll
        for (int o = 16; o; o >>= 1) {
            s.x += __shfl_xor_sync(0xffffffffu, s.x, o);
            s.y += __shfl_xor_sync(0xffffffffu, s.y, o);
            s.z += __shfl_xor_sync(0xffffffffu, s.z, o);
            s.w += __shfl_xor_sync(0xffffffffu, s.w, o);
        }
        if (tid == 0) {
            float4 inv;
            inv.x = __fdividef(1.f, s.x); inv.y = __fdividef(1.f, s.y);
            inv.z = __fdividef(1.f, s.z); inv.w = __fdividef(1.f, s.w);
            sm_sinv = inv;
        }
    }
    __syncthreads();
    float4 sinv = sm_sinv;

    int head = tid >> 5;
    int pi = tid & 31;

    float sinv_h = ((const float*)&sinv)[head];
    float ash = ((const float*)&asn)[head];
    float adh = ((const float*)&ad4)[head];
    float a_self = __expf(leaky(ash + adh)) * sinv_h;
    float2 hv = __half22float2(g_hfeat16[node * 128 + head * 32 + pi]);
    float accx = a_self * hv.x;
    float accy = a_self * hv.y;

    for (int base = 0; base < deg; base += 128) {
        int cnt = min(128, deg - base);
        __syncthreads();
        if (tid < cnt) {
            int src = g_srclist[off + base + tid];
            sm_src[tid] = gbase + src;
            float4 as = __ldg((const float4*)&g_asrc[(gbase + src) * 4]);
            float4 al;
            al.x = __expf(leaky(as.x + ad4.x)) * sinv.x;
            al.y = __expf(leaky(as.y + ad4.y)) * sinv.y;
            al.z = __expf(leaky(as.z + ad4.z)) * sinv.z;
            al.w = __expf(leaky(as.w + ad4.w)) * sinv.w;
            sm_alpha[tid] = al;
        }
        __syncthreads();
        const float* alp = (const float*)sm_alpha;
#pragma unroll 4
        for (int j = 0; j < cnt; j++) {
            int sg = sm_src[j];
            float a = alp[j * 4 + head];
            float2 f = __half22float2(__ldg(&g_hfeat16[sg * 128 + head * 32 + pi]));
            accx += a * f.x;
            accy += a * f.y;
        }
    }

    sred[tid * 2] = accx;
    sred[tid * 2 + 1] = accy;
    __syncthreads();
    if (tid < 32) {
        float vx = sred[tid * 2] + sred[64 + tid * 2] + sred[128 + tid * 2] + sred[192 + tid * 2];
        float vy = sred[tid * 2 + 1] + sred[64 + tid * 2 + 1] + sred[128 + tid * 2 + 1] + sred[192 + tid * 2 + 1];
        float2 b = *(const float2*)&bias[tid * 2];
        vx = vx * 0.25f + b.x;
        vy = vy * 0.25f + b.y;
        if (relu_flag) { vx = fmaxf(vx, 0.f); vy = fmaxf(vy, 0.f); }
        float2 o = make_float2(vx, vy);
        if (which == 0) *(float2*)&g_gat1[node * 64 + tid * 2] = o;
        else            *(float2*)&g_gat2[node * 64 + tid * 2] = o;
    }
}

// -------------------- GRU input matmul (all t), register tiled ------------------
__global__ __launch_bounds__(192)
void gi_kernel(const float* __restrict__ bih0) {
    __shared__ float xsT[64 * 68];
    int t = threadIdx.x;
    int cq = t % 48, rq = t / 48;
    int rowbase = blockIdx.x * 64;

    for (int linear = t; linear < 4096; linear += 192) {
        int r = linear >> 6, k = linear & 63;
        int row = rowbase + r;
        int tt = row / BN, bn = row % BN;
        int b = bn / NN, n = bn % NN;
        xsT[k * 68 + r] = g_gat2[((b * NT + tt) * NN + n) * 64 + k];
    }
    __syncthreads();

    const float4* Wv = (const float4*)g_wih0T;
    float4 acc[16];
#pragma unroll
    for (int i = 0; i < 16; i++) acc[i] = make_float4(0.f, 0.f, 0.f, 0.f);
    int rbase = rq * 16;
    for (int k = 0; k < 64; k++) {
        float4 w = __ldg(&Wv[k * 48 + cq]);
        const float* xk = &xsT[k * 68 + rbase];
#pragma unroll
        for (int i = 0; i < 4; i++) {
            float4 xv = *(const float4*)&xk[i * 4];
            acc[i * 4 + 0].x += xv.x * w.x; acc[i * 4 + 0].y += xv.x * w.y;
            acc[i * 4 + 0].z += xv.x * w.z; acc[i * 4 + 0].w += xv.x * w.w;
            acc[i * 4 + 1].x += xv.y * w.x; acc[i * 4 + 1].y += xv.y * w.y;
            acc[i * 4 + 1].z += xv.y * w.z; acc[i * 4 + 1].w += xv.y * w.w;
            acc[i * 4 + 2].x += xv.z * w.x; acc[i * 4 + 2].y += xv.z * w.y;
            acc[i * 4 + 2].z += xv.z * w.z; acc[i * 4 + 2].w += xv.z * w.w;
            acc[i * 4 + 3].x += xv.w * w.x; acc[i * 4 + 3].y += xv.w * w.y;
            acc[i * 4 + 3].z += xv.w * w.z; acc[i * 4 + 3].w += xv.w * w.w;
        }
    }
    float4 bj = __ldg((const float4*)&bih0[cq * 4]);
#pragma unroll
    for (int i = 0; i < 16; i++) {
        float4 v = acc[i];
        v.x += bj.x; v.y += bj.y; v.z += bj.z; v.w += bj.w;
        *(float4*)&g_gi[(rowbase + rbase + i) * 192 + cq * 4] = v;
    }
}

// -------------------- fused 2-layer GRU step (register tiled, R=16) -------------
__global__ __launch_bounds__(192)
void gru_step_kernel(const float* __restrict__ bhh0,
                     const float* __restrict__ bih1, const float* __restrict__ bhh1,
                     int t) {
    const int R = 16;
    __shared__ float h1T[64 * 20];   // [k][r] padded
    __shared__ float h2T[64 * 20];
    __shared__ float st[R * 196];
    __shared__ float st2[R * 64];

    int tid = threadIdx.x;
    int cq = tid % 48, rq = tid / 48;
    int rowbase = blockIdx.x * R;
    int cbase = cq * 4;
    int gate = cq >> 4;
    int rb = rq * 4;

    for (int idx = tid; idx < R * 64; idx += 192) {
        int r = idx >> 6, k = idx & 63;
        h1T[k * 20 + r] = g_h1[(rowbase + r) * 64 + k];
        h2T[k * 20 + r] = g_h2[(rowbase + r) * 64 + k];
    }
    __syncthreads();

    const float4* W0 = (const float4*)g_whh0T;
    {
        float4 acc[4];
#pragma unroll
        for (int i = 0; i < 4; i++) acc[i] = make_float4(0.f, 0.f, 0.f, 0.f);
        for (int k = 0; k < 64; k++) {
            float4 w = __ldg(&W0[k * 48 + cq]);
            float4 ra = *(const float4*)&h1T[k * 20 + rb];
            acc[0].x += ra.x * w.x; acc[0].y += ra.x * w.y; acc[0].z += ra.x * w.z; acc[0].w += ra.x * w.w;
            acc[1].x += ra.y * w.x; acc[1].y += ra.y * w.y; acc[1].z += ra.y * w.z; acc[1].w += ra.y * w.w;
            acc[2].x += ra.z * w.x; acc[2].y += ra.z * w.y; acc[2].z += ra.z * w.z; acc[2].w += ra.z * w.w;
            acc[3].x += ra.w * w.x; acc[3].y += ra.w * w.y; acc[3].z += ra.w * w.z; acc[3].w += ra.w * w.w;
        }
        float4 bh = __ldg((const float4*)&bhh0[cbase]);
#pragma unroll
        for (int i = 0; i < 4; i++) {
            int r = rb + i;
            float4 gi = __ldg((const float4*)&g_gi[(t * BN + rowbase + r) * 192 + cbase]);
            float4 gh;
            gh.x = acc[i].x + bh.x; gh.y = acc[i].y + bh.y;
            gh.z = acc[i].z + bh.z; gh.w = acc[i].w + bh.w;
            if (gate < 2) {
                float4 v = make_float4(gi.x + gh.x, gi.y + gh.y, gi.z + gh.z, gi.w + gh.w);
                *(float4*)&st[r * 196 + cbase] = v;
            } else {
                *(float4*)&st[r * 196 + cbase] = gi;
                *(float4*)&st2[r * 64 + (cbase - 128)] = gh;
            }
        }
    }
    __syncthreads();

    for (int idx = tid; idx < R * 64; idx += 192) {
        int r = idx >> 6, c = idx & 63;
        float rg = fsig(st[r * 196 + c]);
        float zg = fsig(st[r * 196 + 64 + c]);
        float nv = ftanh(st[r * 196 + 128 + c] + rg * st2[r * 64 + c]);
        float h1o = h1T[c * 20 + r];
        float h1n = (1.f - zg) * nv + zg * h1o;
        h1T[c * 20 + r] = h1n;
        g_h1[(rowbase + r) * 64 + c] = h1n;
    }
    __syncthreads();

    const float4* Wi1 = (const float4*)g_wih1T;
    const float4* Wh1 = (const float4*)g_whh1T;
    {
        float4 acci[4], acch[4];
#pragma unroll
        for (int i = 0; i < 4; i++) {
            acci[i] = make_float4(0.f, 0.f, 0.f, 0.f);
            acch[i] = make_float4(0.f, 0.f, 0.f, 0.f);
        }
        for (int k = 0; k < 64; k++) {
            float4 wi = __ldg(&Wi1[k * 48 + cq]);
            float4 wh = __ldg(&Wh1[k * 48 + cq]);
            float4 a1 = *(const float4*)&h1T[k * 20 + rb];
            float4 a2 = *(const float4*)&h2T[k * 20 + rb];
            acci[0].x += a1.x * wi.x; acci[0].y += a1.x * wi.y; acci[0].z += a1.x * wi.z; acci[0].w += a1.x * wi.w;
            acci[1].x += a1.y * wi.x; acci[1].y += a1.y * wi.y; acci[1].z += a1.y * wi.z; acci[1].w += a1.y * wi.w;
            acci[2].x += a1.z * wi.x; acci[2].y += a1.z * wi.y; acci[2].z += a1.z * wi.z; acci[2].w += a1.z * wi.w;
            acci[3].x += a1.w * wi.x; acci[3].y += a1.w * wi.y; acci[3].z += a1.w * wi.z; acci[3].w += a1.w * wi.w;
            acch[0].x += a2.x * wh.x; acch[0].y += a2.x * wh.y; acch[0].z += a2.x * wh.z; acch[0].w += a2.x * wh.w;
            acch[1].x += a2.y * wh.x; acch[1].y += a2.y * wh.y; acch[1].z += a2.y * wh.z; acch[1].w += a2.y * wh.w;
            acch[2].x += a2.z * wh.x; acch[2].y += a2.z * wh.y; acch[2].z += a2.z * wh.z; acch[2].w += a2.z * wh.w;
            acch[3].x += a2.w * wh.x; acch[3].y += a2.w * wh.y; acch[3].z += a2.w * wh.z; acch[3].w += a2.w * wh.w;
        }
        float4 bi = __ldg((const float4*)&bih1[cbase]);
        float4 bh = __ldg((const float4*)&bhh1[cbase]);
#pragma unroll
        for (int i = 0; i < 4; i++) {
            int r = rb + i;
            float4 gi, gh;
            gi.x = acci[i].x + bi.x; gi.y = acci[i].y + bi.y;
            gi.z = acci[i].z + bi.z; gi.w = acci[i].w + bi.w;
            gh.x = acch[i].x + bh.x; gh.y = acch[i].y + bh.y;
            gh.z = acch[i].z + bh.z; gh.w = acch[i].w + bh.w;
            if (gate < 2) {
                float4 v = make_float4(gi.x + gh.x, gi.y + gh.y, gi.z + gh.z, gi.w + gh.w);
                *(float4*)&st[r * 196 + cbase] = v;
            } else {
                *(float4*)&st[r * 196 + cbase] = gi;
                *(float4*)&st2[r * 64 + (cbase - 128)] = gh;
            }
        }
    }
    __syncthreads();

    for (int idx = tid; idx < R * 64; idx += 192) {
        int r = idx >> 6, c = idx & 63;
        float rg = fsig(st[r * 196 + c]);
        float zg = fsig(st[r * 196 + 64 + c]);
        float nv = ftanh(st[r * 196 + 128 + c] + rg * st2[r * 64 + c]);
        float h2o = h2T[c * 20 + r];
        float h2n = (1.f - zg) * nv + zg * h2o;
        g_h2[(rowbase + r) * 64 + c] = h2n;
    }
}

// -------------------- final MLP --------------------------------------------------
__global__ __launch_bounds__(64)
void mlp_kernel(const float* __restrict__ pW1, const float* __restrict__ pb1,
                const float* __restrict__ pW2, const float* __restrict__ pb2,
                float* __restrict__ out) {
    __shared__ float hs[64 * 64];
    __shared__ float mid[64 * 64];
    int tid = threadIdx.x;
    int rowbase = blockIdx.x * 64;
    int rows = min(64, BN - rowbase);
    for (int i = tid; i < 64 * 64; i += 64)
        hs[i] = (i < rows * 64) ? g_h2[rowbase * 64 + i] : 0.f;
    __syncthreads();
    float acc[64];
#pragma unroll
    for (int r = 0; r < 64; r++) acc[r] = 0.f;
    for (int k = 0; k < 64; k++) {
        float w = pW1[k * 64 + tid];
#pragma unroll
        for (int r = 0; r < 64; r++) acc[r] += hs[r * 64 + k] * w;
    }
    float b = pb1[tid];
    for (int r = 0; r < 64; r++)
        mid[r * 64 + tid] = fmaxf(acc[r] + b, 0.f);
    __syncthreads();
    for (int idx = tid; idx < rows * 10; idx += 64) {
        int r = idx / 10, o = idx % 10;
        float a = pb2[o];
        for (int k = 0; k < 64; k++) a += mid[r * 64 + k] * pW2[k * 10 + o];
        out[(rowbase + r) * 10 + o] = a;
    }
}

// -------------------- launch ------------------------------------------------------
extern "C" void kernel_launch(void* const* d_in, const int* in_sizes, int n_in,
                              void* d_out, int out_size) {
    const float* x    = (const float*)d_in[0];
    const int*   ei   = (const int*)  d_in[1];
    const float* W1   = (const float*)d_in[3];
    const float* as1  = (const float*)d_in[4];
    const float* ad1  = (const float*)d_in[5];
    const float* b1   = (const float*)d_in[6];
    const float* W2   = (const float*)d_in[7];
    const float* as2  = (const float*)d_in[8];
    const float* ad2  = (const float*)d_in[9];
    const float* b2   = (const float*)d_in[10];
    const float* Wih0 = (const float*)d_in[13];
    const float* Whh0 = (const float*)d_in[14];
    const float* bih0 = (const float*)d_in[15];
    const float* bhh0 = (const float*)d_in[16];
    const float* Wih1 = (const float*)d_in[17];
    const float* Whh1 = (const float*)d_in[18];
    const float* bih1 = (const float*)d_in[19];
    const float* bhh1 = (const float*)d_in[20];
    const float* pW1  = (const float*)d_in[21];
    const float* pb1  = (const float*)d_in[22];
    const float* pW2  = (const float*)d_in[23];
    const float* pb2  = (const float*)d_in[24];
    float* out = (float*)d_out;

    init_kernel<<<256, 256>>>();
    wtrans_kernel<<<48, 256>>>(Whh0, Wih1, Whh1, Wih0);
    hist_kernel<<<2000, 256>>>(ei);
    scan_kernel<<<32, 1024>>>();
    scatter_kernel<<<2000, 256>>>(ei);

    // GAT layer 1
    prologue_kernel<<<GN / 64, 256>>>(x, W1, as1, ad1, 0);
    aggregate_kernel<<<GN, 128>>>(b1, 1, 0);

    // GAT layer 2
    prologue_kernel<<<GN / 64, 256>>>(nullptr, W2, as2, ad2, 1);
    aggregate_kernel<<<GN, 128>>>(b2, 0, 1);

    // GRU
    gi_kernel<<<(NT * BN) / 64, 192>>>(bih0);
    for (int t = 0; t < NT; t++)
        gru_step_kernel<<<BN / 16, 192>>>(bhh0, bih1, bhh1, t);

    // head
    mlp_kernel<<<(BN + 63) / 64, 64>>>(pW1, pb1, pW2, pb2, out);
}

// round 6
// speedup vs baseline: 1.5168x; 1.1531x over previous
#include <cuda_runtime.h>
#include <cuda_fp16.h>
#include <math.h>

#define NB    4
#define NN    1000
#define NT    8
#define NF    64
#define NH    64
#define NHEAD 4
#define NE    16000
#define NG    32
#define GN    32000
#define BN    4000
#define TOTE  512000
#define NEG_SLOPE 0.2f

// -------------------- scratch ------------------------------------------------
__device__ __half2 g_hfeat16[GN * 128];   // h = in @ W, fp16 pairs [node][128]
__device__ float g_asrc[GN * 4];
__device__ float g_adst[GN * 4];
__device__ float g_gat1[GN * 64];
__device__ float g_gat2[GN * 64];
__device__ float g_gi[NT * BN * 192];
__device__ float g_h1[BN * 64];
__device__ float g_h2[BN * 64];
__device__ int   g_deg[GN];
__device__ int   g_offs[GN + 1];
__device__ int   g_cursor[GN];
__device__ int   g_srclist[TOTE];
// transposed weights [k][j]
__device__ float g_whh0T[64 * 192];
__device__ float g_wih1T[64 * 192];
__device__ float g_whh1T[64 * 192];
__device__ float g_wih0T[64 * 192];

// -------------------- fast math ----------------------------------------------
__device__ __forceinline__ float leaky(float x) { return fmaxf(x, NEG_SLOPE * x); }
__device__ __forceinline__ float fsig(float x) {
    float e = __expf(-fabsf(x));
    float r = __fdividef(1.f, 1.f + e);
    return x >= 0.f ? r : r * e;
}
__device__ __forceinline__ float ftanh(float x) {
    float e = __expf(-2.f * fabsf(x));
    float t = 1.f - __fdividef(2.f * e, 1.f + e);
    return x >= 0.f ? t : -t;
}

// -------------------- init ----------------------------------------------------
__global__ void init_kernel() {
    int total = GN + BN * 64 * 2;
    for (int i = blockIdx.x * blockDim.x + threadIdx.x; i < total;
         i += gridDim.x * blockDim.x) {
        if (i < GN) g_deg[i] = 0;
        else if (i < GN + BN * 64) g_h1[i - GN] = 0.f;
        else g_h2[i - GN - BN * 64] = 0.f;
    }
}

__global__ void wtrans_kernel(const float* __restrict__ Whh0,
                              const float* __restrict__ Wih1,
                              const float* __restrict__ Whh1,
                              const float* __restrict__ Wih0) {
    int i = blockIdx.x * blockDim.x + threadIdx.x;
    if (i >= 12288) return;
    int j = i / 64, k = i % 64;
    g_whh0T[k * 192 + j] = Whh0[i];
    g_wih1T[k * 192 + j] = Wih1[i];
    g_whh1T[k * 192 + j] = Whh1[i];
    g_wih0T[k * 192 + j] = Wih0[i];
}

// -------------------- CSR build ------------------------------------------------
__global__ void hist_kernel(const int* __restrict__ ei) {
    for (int e = blockIdx.x * blockDim.x + threadIdx.x; e < TOTE;
         e += gridDim.x * blockDim.x) {
        int g = e / NE, el = e % NE;
        int dst = ei[(g * 2 + 1) * NE + el];
        atomicAdd(&g_deg[g * NN + dst], 1);
    }
}

// per-graph scan: 32 blocks x 1024 threads, one node per thread.
__global__ void scan_kernel() {
    __shared__ int wsum[32];
    int g = blockIdx.x;
    int tid = threadIdx.x, lane = tid & 31, wid = tid >> 5;
    int d = (tid < NN) ? g_deg[g * NN + tid] : 0;
    int s = d;
#pragma unroll
    for (int o = 1; o < 32; o <<= 1) {
        int v = __shfl_up_sync(0xffffffffu, s, o);
        if (lane >= o) s += v;
    }
    if (lane == 31) wsum[wid] = s;
    __syncthreads();
    if (wid == 0) {
        int v = wsum[lane];
#pragma unroll
        for (int o = 1; o < 32; o <<= 1) {
            int u = __shfl_up_sync(0xffffffffu, v, o);
            if (lane >= o) v += u;
        }
        wsum[lane] = v;
    }
    __syncthreads();
    int incl = s + (wid > 0 ? wsum[wid - 1] : 0);
    int excl = incl - d;
    if (tid < NN) {
        int node = g * NN + tid;
        int off = g * NE + excl;
        g_offs[node] = off;
        g_cursor[node] = off;
    }
    if (g == 0 && tid == 0) g_offs[GN] = TOTE;
}

__global__ void scatter_kernel(const int* __restrict__ ei) {
    for (int e = blockIdx.x * blockDim.x + threadIdx.x; e < TOTE;
         e += gridDim.x * blockDim.x) {
        int g = e / NE, el = e % NE;
        int src = ei[(g * 2 + 0) * NE + el];
        int dst = ei[(g * 2 + 1) * NE + el];
        int pos = atomicAdd(&g_cursor[g * NN + dst], 1);
        g_srclist[pos] = src;
    }
}

// -------------------- GAT prologue + attention scalars -------------------------
// Block: 64 nodes x 256 cols. 256 threads; cq = t&63 -> 4 cols, rq = t>>6 -> 16 rows.
__global__ __launch_bounds__(256)
void prologue_kernel(const float* __restrict__ in, const float* __restrict__ W,
                     const float* __restrict__ att_src, const float* __restrict__ att_dst,
                     int mode) {
    __shared__ float xsT[64 * 68];   // [k][r], padded
    int t = threadIdx.x;
    int cq = t & 63, rq = t >> 6;
    int lane = t & 31;
    int nodebase = blockIdx.x * 64;

    for (int linear = t; linear < 4096; linear += 256) {
        int r = linear >> 6, k = linear & 63;
        int node = nodebase + r;
        float v;
        if (mode == 0) {
            int gg = node / NN, n = node % NN;
            int b = gg >> 3, tt = gg & 7;
            v = in[((b * NN + n) * NT + tt) * NF + k];
        } else {
            v = g_gat1[node * 64 + k];
        }
        xsT[k * 68 + r] = v;
    }
    __syncthreads();

    const float4* Wv = (const float4*)W;
    float4 acc[16];
#pragma unroll
    for (int i = 0; i < 16; i++) acc[i] = make_float4(0.f, 0.f, 0.f, 0.f);

    int rbase = rq * 16;
    for (int k = 0; k < 64; k++) {
        float4 w = __ldg(&Wv[k * 64 + cq]);
        const float* xk = &xsT[k * 68 + rbase];
#pragma unroll
        for (int i = 0; i < 4; i++) {
            float4 xv = *(const float4*)&xk[i * 4];
            acc[i * 4 + 0].x += xv.x * w.x; acc[i * 4 + 0].y += xv.x * w.y;
            acc[i * 4 + 0].z += xv.x * w.z; acc[i * 4 + 0].w += xv.x * w.w;
            acc[i * 4 + 1].x += xv.y * w.x; acc[i * 4 + 1].y += xv.y * w.y;
            acc[i * 4 + 1].z += xv.y * w.z; acc[i * 4 + 1].w += xv.y * w.w;
            acc[i * 4 + 2].x += xv.z * w.x; acc[i * 4 + 2].y += xv.z * w.y;
            acc[i * 4 + 2].z += xv.z * w.z; acc[i * 4 + 2].w += xv.z * w.w;
            acc[i * 4 + 3].x += xv.w * w.x; acc[i * 4 + 3].y += xv.w * w.y;
            acc[i * 4 + 3].z += xv.w * w.z; acc[i * 4 + 3].w += xv.w * w.w;
        }
    }

    float4 as4 = __ldg((const float4*)&att_src[cq * 4]);
    float4 ad4 = __ldg((const float4*)&att_dst[cq * 4]);
    int hd = cq >> 4;

#pragma unroll
    for (int i = 0; i < 16; i++) {
        int node = nodebase + rbase + i;
        float4 a = acc[i];

        __half2 h0 = __floats2half2_rn(a.x, a.y);
        __half2 h1 = __floats2half2_rn(a.z, a.w);
        uint2 u;
        u.x = *(unsigned*)&h0;
        u.y = *(unsigned*)&h1;
        *(uint2*)&g_hfeat16[node * 128 + cq * 2] = u;

        float ps = a.x * as4.x + a.y * as4.y + a.z * as4.z + a.w * as4.w;
        float pd = a.x * ad4.x + a.y * ad4.y + a.z * ad4.z + a.w * ad4.w;
#pragma unroll
        for (int o = 8; o; o >>= 1) {
            ps += __shfl_xor_sync(0xffffffffu, ps, o);
            pd += __shfl_xor_sync(0xffffffffu, pd, o);
        }
        if ((lane & 15) == 0) {
            g_asrc[node * 4 + hd] = ps;
            g_adst[node * 4 + hd] = pd;
        }
    }
}

// -------------------- GAT aggregation (single pass, fp16 gather) ----------------
// One node per block, 128 threads. Accumulate unnormalized sum + denominator,
// divide once at the end (softmax without max-shift; logits are small).
__global__ __launch_bounds__(128)
void aggregate_kernel(const float* __restrict__ bias, int relu_flag, int which) {
    __shared__ float4 sm_w[128];
    __shared__ int    sm_src[128];
    __shared__ float  sred[256];

    int node = blockIdx.x;
    int g = node / NN;
    int gbase = g * NN;
    int tid = threadIdx.x;
    int off = g_offs[node];
    int deg = g_offs[node + 1] - off;

    float4 ad4 = *(const float4*)&g_adst[node * 4];
    float4 asn = *(const float4*)&g_asrc[node * 4];

    int head = tid >> 5;
    int pi = tid & 31;

    float ash = ((const float*)&asn)[head];
    float adh = ((const float*)&ad4)[head];
    float w_self = __expf(leaky(ash + adh));
    float2 hv = __half22float2(g_hfeat16[node * 128 + head * 32 + pi]);
    float s = w_self;
    float accx = w_self * hv.x;
    float accy = w_self * hv.y;

    for (int base = 0; base < deg; base += 128) {
        int cnt = min(128, deg - base);
        __syncthreads();
        if (tid < cnt) {
            int src = g_srclist[off + base + tid];
            sm_src[tid] = gbase + src;
            float4 as = __ldg((const float4*)&g_asrc[(gbase + src) * 4]);
            float4 w;
            w.x = __expf(leaky(as.x + ad4.x));
            w.y = __expf(leaky(as.y + ad4.y));
            w.z = __expf(leaky(as.z + ad4.z));
            w.w = __expf(leaky(as.w + ad4.w));
            sm_w[tid] = w;
        }
        __syncthreads();
        const float* alp = (const float*)sm_w;
#pragma unroll 4
        for (int j = 0; j < cnt; j++) {
            int sg = sm_src[j];
            float a = alp[j * 4 + head];
            float2 f = __half22float2(__ldg(&g_hfeat16[sg * 128 + head * 32 + pi]));
            s += a;
            accx += a * f.x;
            accy += a * f.y;
        }
    }

    float inv = __fdividef(1.f, s);
    sred[tid * 2] = accx * inv;
    sred[tid * 2 + 1] = accy * inv;
    __syncthreads();
    if (tid < 32) {
        float vx = sred[tid * 2] + sred[64 + tid * 2] + sred[128 + tid * 2] + sred[192 + tid * 2];
        float vy = sred[tid * 2 + 1] + sred[64 + tid * 2 + 1] + sred[128 + tid * 2 + 1] + sred[192 + tid * 2 + 1];
        float2 b = *(const float2*)&bias[tid * 2];
        vx = vx * 0.25f + b.x;
        vy = vy * 0.25f + b.y;
        if (relu_flag) { vx = fmaxf(vx, 0.f); vy = fmaxf(vy, 0.f); }
        float2 o = make_float2(vx, vy);
        if (which == 0) *(float2*)&g_gat1[node * 64 + tid * 2] = o;
        else            *(float2*)&g_gat2[node * 64 + tid * 2] = o;
    }
}

// -------------------- GRU input matmul (all t), register tiled ------------------
__global__ __launch_bounds__(192)
void gi_kernel(const float* __restrict__ bih0) {
    __shared__ float xsT[64 * 68];
    int t = threadIdx.x;
    int cq = t % 48, rq = t / 48;
    int rowbase = blockIdx.x * 64;

    for (int linear = t; linear < 4096; linear += 192) {
        int r = linear >> 6, k = linear & 63;
        int row = rowbase + r;
        int tt = row / BN, bn = row % BN;
        int b = bn / NN, n = bn % NN;
        xsT[k * 68 + r] = g_gat2[((b * NT + tt) * NN + n) * 64 + k];
    }
    __syncthreads();

    const float4* Wv = (const float4*)g_wih0T;
    float4 acc[16];
#pragma unroll
    for (int i = 0; i < 16; i++) acc[i] = make_float4(0.f, 0.f, 0.f, 0.f);
    int rbase = rq * 16;
    for (int k = 0; k < 64; k++) {
        float4 w = __ldg(&Wv[k * 48 + cq]);
        const float* xk = &xsT[k * 68 + rbase];
#pragma unroll
        for (int i = 0; i < 4; i++) {
            float4 xv = *(const float4*)&xk[i * 4];
            acc[i * 4 + 0].x += xv.x * w.x; acc[i * 4 + 0].y += xv.x * w.y;
            acc[i * 4 + 0].z += xv.x * w.z; acc[i * 4 + 0].w += xv.x * w.w;
            acc[i * 4 + 1].x += xv.y * w.x; acc[i * 4 + 1].y += xv.y * w.y;
            acc[i * 4 + 1].z += xv.y * w.z; acc[i * 4 + 1].w += xv.y * w.w;
            acc[i * 4 + 2].x += xv.z * w.x; acc[i * 4 + 2].y += xv.z * w.y;
            acc[i * 4 + 2].z += xv.z * w.z; acc[i * 4 + 2].w += xv.z * w.w;
            acc[i * 4 + 3].x += xv.w * w.x; acc[i * 4 + 3].y += xv.w * w.y;
            acc[i * 4 + 3].z += xv.w * w.z; acc[i * 4 + 3].w += xv.w * w.w;
        }
    }
    float4 bj = __ldg((const float4*)&bih0[cq * 4]);
#pragma unroll
    for (int i = 0; i < 16; i++) {
        float4 v = acc[i];
        v.x += bj.x; v.y += bj.y; v.z += bj.z; v.w += bj.w;
        *(float4*)&g_gi[(rowbase + rbase + i) * 192 + cq * 4] = v;
    }
}

// -------------------- fused 2-layer GRU step (register tiled, R=8) --------------
// 500 blocks x 192 threads: cq=t%48 (4 cols of 192), rq=t/48 (2 rows each of 8)
__global__ __launch_bounds__(192)
void gru_step_kernel(const float* __restrict__ bhh0,
                     const float* __restrict__ bih1, const float* __restrict__ bhh1,
                     int t) {
    const int R = 8;
    __shared__ float h1T[64 * 10];   // [k][r] padded (stride 10, rb even -> 8B aligned)
    __shared__ float h2T[64 * 10];
    __shared__ float st[R * 196];
    __shared__ float st2[R * 64];

    int tid = threadIdx.x;
    int cq = tid % 48, rq = tid / 48;
    int rowbase = blockIdx.x * R;
    int cbase = cq * 4;
    int gate = cq >> 4;
    int rb = rq * 2;

    for (int idx = tid; idx < R * 64; idx += 192) {
        int r = idx >> 6, k = idx & 63;
        h1T[k * 10 + r] = g_h1[(rowbase + r) * 64 + k];
        h2T[k * 10 + r] = g_h2[(rowbase + r) * 64 + k];
    }
    __syncthreads();

    const float4* W0 = (const float4*)g_whh0T;
    {
        float4 acc[2];
        acc[0] = make_float4(0.f, 0.f, 0.f, 0.f);
        acc[1] = make_float4(0.f, 0.f, 0.f, 0.f);
        for (int k = 0; k < 64; k++) {
            float4 w = __ldg(&W0[k * 48 + cq]);
            float2 ra = *(const float2*)&h1T[k * 10 + rb];
            acc[0].x += ra.x * w.x; acc[0].y += ra.x * w.y; acc[0].z += ra.x * w.z; acc[0].w += ra.x * w.w;
            acc[1].x += ra.y * w.x; acc[1].y += ra.y * w.y; acc[1].z += ra.y * w.z; acc[1].w += ra.y * w.w;
        }
        float4 bh = __ldg((const float4*)&bhh0[cbase]);
#pragma unroll
        for (int i = 0; i < 2; i++) {
            int r = rb + i;
            float4 gi = __ldg((const float4*)&g_gi[(t * BN + rowbase + r) * 192 + cbase]);
            float4 gh;
            gh.x = acc[i].x + bh.x; gh.y = acc[i].y + bh.y;
            gh.z = acc[i].z + bh.z; gh.w = acc[i].w + bh.w;
            if (gate < 2) {
                float4 v = make_float4(gi.x + gh.x, gi.y + gh.y, gi.z + gh.z, gi.w + gh.w);
                *(float4*)&st[r * 196 + cbase] = v;
            } else {
                *(float4*)&st[r * 196 + cbase] = gi;
                *(float4*)&st2[r * 64 + (cbase - 128)] = gh;
            }
        }
    }
    __syncthreads();

    for (int idx = tid; idx < R * 64; idx += 192) {
        int r = idx >> 6, c = idx & 63;
        float rg = fsig(st[r * 196 + c]);
        float zg = fsig(st[r * 196 + 64 + c]);
        float nv = ftanh(st[r * 196 + 128 + c] + rg * st2[r * 64 + c]);
        float h1o = h1T[c * 10 + r];
        float h1n = (1.f - zg) * nv + zg * h1o;
        h1T[c * 10 + r] = h1n;
        g_h1[(rowbase + r) * 64 + c] = h1n;
    }
    __syncthreads();

    const float4* Wi1 = (const float4*)g_wih1T;
    const float4* Wh1 = (const float4*)g_whh1T;
    {
        float4 acci[2], acch[2];
        acci[0] = make_float4(0.f, 0.f, 0.f, 0.f);
        acci[1] = make_float4(0.f, 0.f, 0.f, 0.f);
        acch[0] = make_float4(0.f, 0.f, 0.f, 0.f);
        acch[1] = make_float4(0.f, 0.f, 0.f, 0.f);
        for (int k = 0; k < 64; k++) {
            float4 wi = __ldg(&Wi1[k * 48 + cq]);
            float4 wh = __ldg(&Wh1[k * 48 + cq]);
            float2 a1 = *(const float2*)&h1T[k * 10 + rb];
            float2 a2 = *(const float2*)&h2T[k * 10 + rb];
            acci[0].x += a1.x * wi.x; acci[0].y += a1.x * wi.y; acci[0].z += a1.x * wi.z; acci[0].w += a1.x * wi.w;
            acci[1].x += a1.y * wi.x; acci[1].y += a1.y * wi.y; acci[1].z += a1.y * wi.z; acci[1].w += a1.y * wi.w;
            acch[0].x += a2.x * wh.x; acch[0].y += a2.x * wh.y; acch[0].z += a2.x * wh.z; acch[0].w += a2.x * wh.w;
            acch[1].x += a2.y * wh.x; acch[1].y += a2.y * wh.y; acch[1].z += a2.y * wh.z; acch[1].w += a2.y * wh.w;
        }
        float4 bi = __ldg((const float4*)&bih1[cbase]);
        float4 bh = __ldg((const float4*)&bhh1[cbase]);
#pragma unroll
        for (int i = 0; i < 2; i++) {
            int r = rb + i;
            float4 gi, gh;
            gi.x = acci[i].x + bi.x; gi.y = acci[i].y + bi.y;
            gi.z = acci[i].z + bi.z; gi.w = acci[i].w + bi.w;
            gh.x = acch[i].x + bh.x; gh.y = acch[i].y + bh.y;
            gh.z = acch[i].z + bh.z; gh.w = acch[i].w + bh.w;
            if (gate < 2) {
                float4 v = make_float4(gi.x + gh.x, gi.y + gh.y, gi.z + gh.z, gi.w + gh.w);
                *(float4*)&st[r * 196 + cbase] = v;
            } else {
                *(float4*)&st[r * 196 + cbase] = gi;
                *(float4*)&st2[r * 64 + (cbase - 128)] = gh;
            }
        }
    }
    __syncthreads();

    for (int idx = tid; idx < R * 64; idx += 192) {
        int r = idx >> 6, c = idx & 63;
        float rg = fsig(st[r * 196 + c]);
        float zg = fsig(st[r * 196 + 64 + c]);
        float nv = ftanh(st[r * 196 + 128 + c] + rg * st2[r * 64 + c]);
        float h2o = h2T[c * 10 + r];
        float h2n = (1.f - zg) * nv + zg * h2o;
        g_h2[(rowbase + r) * 64 + c] = h2n;
    }
}

// -------------------- final MLP --------------------------------------------------
__global__ __launch_bounds__(64)
void mlp_kernel(const float* __restrict__ pW1, const float* __restrict__ pb1,
                const float* __restrict__ pW2, const float* __restrict__ pb2,
                float* __restrict__ out) {
    __shared__ float hs[64 * 64];
    __shared__ float mid[64 * 64];
    int tid = threadIdx.x;
    int rowbase = blockIdx.x * 64;
    int rows = min(64, BN - rowbase);
    for (int i = tid; i < 64 * 64; i += 64)
        hs[i] = (i < rows * 64) ? g_h2[rowbase * 64 + i] : 0.f;
    __syncthreads();
    float acc[64];
#pragma unroll
    for (int r = 0; r < 64; r++) acc[r] = 0.f;
    for (int k = 0; k < 64; k++) {
        float w = pW1[k * 64 + tid];
#pragma unroll
        for (int r = 0; r < 64; r++) acc[r] += hs[r * 64 + k] * w;
    }
    float b = pb1[tid];
    for (int r = 0; r < 64; r++)
        mid[r * 64 + tid] = fmaxf(acc[r] + b, 0.f);
    __syncthreads();
    for (int idx = tid; idx < rows * 10; idx += 64) {
        int r = idx / 10, o = idx % 10;
        float a = pb2[o];
        for (int k = 0; k < 64; k++) a += mid[r * 64 + k] * pW2[k * 10 + o];
        out[(rowbase + r) * 10 + o] = a;
    }
}

// -------------------- launch ------------------------------------------------------
extern "C" void kernel_launch(void* const* d_in, const int* in_sizes, int n_in,
                              void* d_out, int out_size) {
    const float* x    = (const float*)d_in[0];
    const int*   ei   = (const int*)  d_in[1];
    const float* W1   = (const float*)d_in[3];
    const float* as1  = (const float*)d_in[4];
    const float* ad1  = (const float*)d_in[5];
    const float* b1   = (const float*)d_in[6];
    const float* W2   = (const float*)d_in[7];
    const float* as2  = (const float*)d_in[8];
    const float* ad2  = (const float*)d_in[9];
    const float* b2   = (const float*)d_in[10];
    const float* Wih0 = (const float*)d_in[13];
    const float* Whh0 = (const float*)d_in[14];
    const float* bih0 = (const float*)d_in[15];
    const float* bhh0 = (const float*)d_in[16];
    const float* Wih1 = (const float*)d_in[17];
    const float* Whh1 = (const float*)d_in[18];
    const float* bih1 = (const float*)d_in[19];
    const float* bhh1 = (const float*)d_in[20];
    const float* pW1  = (const float*)d_in[21];
    const float* pb1  = (const float*)d_in[22];
    const float* pW2  = (const float*)d_in[23];
    const float* pb2  = (const float*)d_in[24];
    float* out = (float*)d_out;

    init_kernel<<<256, 256>>>();
    wtrans_kernel<<<48, 256>>>(Whh0, Wih1, Whh1, Wih0);
    hist_kernel<<<2000, 256>>>(ei);
    scan_kernel<<<32, 1024>>>();
    scatter_kernel<<<2000, 256>>>(ei);

    // GAT layer 1
    prologue_kernel<<<GN / 64, 256>>>(x, W1, as1, ad1, 0);
    aggregate_kernel<<<GN, 128>>>(b1, 1, 0);

    // GAT layer 2
    prologue_kernel<<<GN / 64, 256>>>(nullptr, W2, as2, ad2, 1);
    aggregate_kernel<<<GN, 128>>>(b2, 0, 1);

    // GRU
    gi_kernel<<<(NT * BN) / 64, 192>>>(bih0);
    for (int t = 0; t < NT; t++)
        gru_step_kernel<<<BN / 8, 192>>>(bhh0, bih1, bhh1, t);

    // head
    mlp_kernel<<<(BN + 63) / 64, 64>>>(pW1, pb1, pW2, pb2, out);
}

// round 7
// speedup vs baseline: 1.7325x; 1.1422x over previous
#include <cuda_runtime.h>
#include <cuda_fp16.h>
#include <math.h>

#define NB    4
#define NN    1000
#define NT    8
#define NF    64
#define NH    64
#define NHEAD 4
#define NE    16000
#define NG    32
#define GN    32000
#define BN    4000
#define TOTE  512000
#define NEG_SLOPE 0.2f

// -------------------- scratch ------------------------------------------------
__device__ __half2 g_hfeat16[GN * 128];   // h = in @ W, fp16 pairs [node][128]
__device__ float g_asrc[GN * 4];
__device__ float g_adst[GN * 4];
__device__ float g_gat1[GN * 64];
__device__ float g_gat2[GN * 64];
__device__ float g_gi[NT * BN * 192];
__device__ int   g_deg[GN];
__device__ int   g_offs[GN + 1];
__device__ int   g_cursor[GN];
__device__ int   g_srclist[TOTE];
// transposed weights [k][j]
__device__ float g_whh0T[64 * 192];
__device__ float g_wih1T[64 * 192];
__device__ float g_whh1T[64 * 192];
__device__ float g_wih0T[64 * 192];

// -------------------- fast math ----------------------------------------------
__device__ __forceinline__ float leaky(float x) { return fmaxf(x, NEG_SLOPE * x); }
__device__ __forceinline__ float fsig(float x) {
    float e = __expf(-fabsf(x));
    float r = __fdividef(1.f, 1.f + e);
    return x >= 0.f ? r : r * e;
}
__device__ __forceinline__ float ftanh(float x) {
    float e = __expf(-2.f * fabsf(x));
    float t = 1.f - __fdividef(2.f * e, 1.f + e);
    return x >= 0.f ? t : -t;
}

// -------------------- init ----------------------------------------------------
__global__ void init_kernel() {
    int i = blockIdx.x * blockDim.x + threadIdx.x;
    if (i < GN) g_deg[i] = 0;
}

__global__ void wtrans_kernel(const float* __restrict__ Whh0,
                              const float* __restrict__ Wih1,
                              const float* __restrict__ Whh1,
                              const float* __restrict__ Wih0) {
    int i = blockIdx.x * blockDim.x + threadIdx.x;
    if (i >= 12288) return;
    int j = i / 64, k = i % 64;
    g_whh0T[k * 192 + j] = Whh0[i];
    g_wih1T[k * 192 + j] = Wih1[i];
    g_whh1T[k * 192 + j] = Whh1[i];
    g_wih0T[k * 192 + j] = Wih0[i];
}

// -------------------- CSR build (int4 vectorized) -------------------------------
__global__ void hist_kernel(const int* __restrict__ ei) {
    int e4 = blockIdx.x * blockDim.x + threadIdx.x;    // 128K threads, 4 edges each
    if (e4 >= TOTE / 4) return;
    int e = e4 * 4;
    int g = e / NE, el = e % NE;
    int4 d = __ldg((const int4*)&ei[(g * 2 + 1) * NE + el]);
    int base = g * NN;
    atomicAdd(&g_deg[base + d.x], 1);
    atomicAdd(&g_deg[base + d.y], 1);
    atomicAdd(&g_deg[base + d.z], 1);
    atomicAdd(&g_deg[base + d.w], 1);
}

// per-graph scan: 32 blocks x 1024 threads, one node per thread.
__global__ void scan_kernel() {
    __shared__ int wsum[32];
    int g = blockIdx.x;
    int tid = threadIdx.x, lane = tid & 31, wid = tid >> 5;
    int d = (tid < NN) ? g_deg[g * NN + tid] : 0;
    int s = d;
#pragma unroll
    for (int o = 1; o < 32; o <<= 1) {
        int v = __shfl_up_sync(0xffffffffu, s, o);
        if (lane >= o) s += v;
    }
    if (lane == 31) wsum[wid] = s;
    __syncthreads();
    if (wid == 0) {
        int v = wsum[lane];
#pragma unroll
        for (int o = 1; o < 32; o <<= 1) {
            int u = __shfl_up_sync(0xffffffffu, v, o);
            if (lane >= o) v += u;
        }
        wsum[lane] = v;
    }
    __syncthreads();
    int incl = s + (wid > 0 ? wsum[wid - 1] : 0);
    int excl = incl - d;
    if (tid < NN) {
        int node = g * NN + tid;
        int off = g * NE + excl;
        g_offs[node] = off;
        g_cursor[node] = off;
    }
    if (g == 0 && tid == 0) g_offs[GN] = TOTE;
}

__global__ void scatter_kernel(const int* __restrict__ ei) {
    int e4 = blockIdx.x * blockDim.x + threadIdx.x;
    if (e4 >= TOTE / 4) return;
    int e = e4 * 4;
    int g = e / NE, el = e % NE;
    int4 sv = __ldg((const int4*)&ei[(g * 2 + 0) * NE + el]);
    int4 dv = __ldg((const int4*)&ei[(g * 2 + 1) * NE + el]);
    int base = g * NN;
    int p;
    p = atomicAdd(&g_cursor[base + dv.x], 1); g_srclist[p] = sv.x;
    p = atomicAdd(&g_cursor[base + dv.y], 1); g_srclist[p] = sv.y;
    p = atomicAdd(&g_cursor[base + dv.z], 1); g_srclist[p] = sv.z;
    p = atomicAdd(&g_cursor[base + dv.w], 1); g_srclist[p] = sv.w;
}

// -------------------- GAT prologue + attention scalars -------------------------
// Block: 64 nodes x 256 cols. 256 threads; cq = t&63 -> 4 cols, rq = t>>6 -> 16 rows.
__global__ __launch_bounds__(256)
void prologue_kernel(const float* __restrict__ in, const float* __restrict__ W,
                     const float* __restrict__ att_src, const float* __restrict__ att_dst,
                     int mode) {
    __shared__ float xsT[64 * 68];   // [k][r], padded
    int t = threadIdx.x;
    int cq = t & 63, rq = t >> 6;
    int lane = t & 31;
    int nodebase = blockIdx.x * 64;

    for (int linear = t; linear < 4096; linear += 256) {
        int r = linear >> 6, k = linear & 63;
        int node = nodebase + r;
        float v;
        if (mode == 0) {
            int gg = node / NN, n = node % NN;
            int b = gg >> 3, tt = gg & 7;
            v = in[((b * NN + n) * NT + tt) * NF + k];
        } else {
            v = g_gat1[node * 64 + k];
        }
        xsT[k * 68 + r] = v;
    }
    __syncthreads();

    const float4* Wv = (const float4*)W;
    float4 acc[16];
#pragma unroll
    for (int i = 0; i < 16; i++) acc[i] = make_float4(0.f, 0.f, 0.f, 0.f);

    int rbase = rq * 16;
    for (int k = 0; k < 64; k++) {
        float4 w = __ldg(&Wv[k * 64 + cq]);
        const float* xk = &xsT[k * 68 + rbase];
#pragma unroll
        for (int i = 0; i < 4; i++) {
            float4 xv = *(const float4*)&xk[i * 4];
            acc[i * 4 + 0].x += xv.x * w.x; acc[i * 4 + 0].y += xv.x * w.y;
            acc[i * 4 + 0].z += xv.x * w.z; acc[i * 4 + 0].w += xv.x * w.w;
            acc[i * 4 + 1].x += xv.y * w.x; acc[i * 4 + 1].y += xv.y * w.y;
            acc[i * 4 + 1].z += xv.y * w.z; acc[i * 4 + 1].w += xv.y * w.w;
            acc[i * 4 + 2].x += xv.z * w.x; acc[i * 4 + 2].y += xv.z * w.y;
            acc[i * 4 + 2].z += xv.z * w.z; acc[i * 4 + 2].w += xv.z * w.w;
            acc[i * 4 + 3].x += xv.w * w.x; acc[i * 4 + 3].y += xv.w * w.y;
            acc[i * 4 + 3].z += xv.w * w.z; acc[i * 4 + 3].w += xv.w * w.w;
        }
    }

    float4 as4 = __ldg((const float4*)&att_src[cq * 4]);
    float4 ad4 = __ldg((const float4*)&att_dst[cq * 4]);
    int hd = cq >> 4;

#pragma unroll
    for (int i = 0; i < 16; i++) {
        int node = nodebase + rbase + i;
        float4 a = acc[i];

        __half2 h0 = __floats2half2_rn(a.x, a.y);
        __half2 h1 = __floats2half2_rn(a.z, a.w);
        uint2 u;
        u.x = *(unsigned*)&h0;
        u.y = *(unsigned*)&h1;
        *(uint2*)&g_hfeat16[node * 128 + cq * 2] = u;

        float ps = a.x * as4.x + a.y * as4.y + a.z * as4.z + a.w * as4.w;
        float pd = a.x * ad4.x + a.y * ad4.y + a.z * ad4.z + a.w * ad4.w;
#pragma unroll
        for (int o = 8; o; o >>= 1) {
            ps += __shfl_xor_sync(0xffffffffu, ps, o);
            pd += __shfl_xor_sync(0xffffffffu, pd, o);
        }
        if ((lane & 15) == 0) {
            g_asrc[node * 4 + hd] = ps;
            g_adst[node * 4 + hd] = pd;
        }
    }
}

// -------------------- GAT aggregation (single pass, fp16 gather) ----------------
__global__ __launch_bounds__(128)
void aggregate_kernel(const float* __restrict__ bias, int relu_flag, int which) {
    __shared__ float4 sm_w[128];
    __shared__ int    sm_src[128];
    __shared__ float  sred[256];

    int node = blockIdx.x;
    int g = node / NN;
    int gbase = g * NN;
    int tid = threadIdx.x;
    int off = g_offs[node];
    int deg = g_offs[node + 1] - off;

    float4 ad4 = *(const float4*)&g_adst[node * 4];
    float4 asn = *(const float4*)&g_asrc[node * 4];

    int head = tid >> 5;
    int pi = tid & 31;

    float ash = ((const float*)&asn)[head];
    float adh = ((const float*)&ad4)[head];
    float w_self = __expf(leaky(ash + adh));
    float2 hv = __half22float2(g_hfeat16[node * 128 + head * 32 + pi]);
    float s = w_self;
    float accx = w_self * hv.x;
    float accy = w_self * hv.y;

    for (int base = 0; base < deg; base += 128) {
        int cnt = min(128, deg - base);
        __syncthreads();
        if (tid < cnt) {
            int src = g_srclist[off + base + tid];
            sm_src[tid] = gbase + src;
            float4 as = __ldg((const float4*)&g_asrc[(gbase + src) * 4]);
            float4 w;
            w.x = __expf(leaky(as.x + ad4.x));
            w.y = __expf(leaky(as.y + ad4.y));
            w.z = __expf(leaky(as.z + ad4.z));
            w.w = __expf(leaky(as.w + ad4.w));
            sm_w[tid] = w;
        }
        __syncthreads();
        const float* alp = (const float*)sm_w;
#pragma unroll 4
        for (int j = 0; j < cnt; j++) {
            int sg = sm_src[j];
            float a = alp[j * 4 + head];
            float2 f = __half22float2(__ldg(&g_hfeat16[sg * 128 + head * 32 + pi]));
            s += a;
            accx += a * f.x;
            accy += a * f.y;
        }
    }

    float inv = __fdividef(1.f, s);
    sred[tid * 2] = accx * inv;
    sred[tid * 2 + 1] = accy * inv;
    __syncthreads();
    if (tid < 32) {
        float vx = sred[tid * 2] + sred[64 + tid * 2] + sred[128 + tid * 2] + sred[192 + tid * 2];
        float vy = sred[tid * 2 + 1] + sred[64 + tid * 2 + 1] + sred[128 + tid * 2 + 1] + sred[192 + tid * 2 + 1];
        float2 b = *(const float2*)&bias[tid * 2];
        vx = vx * 0.25f + b.x;
        vy = vy * 0.25f + b.y;
        if (relu_flag) { vx = fmaxf(vx, 0.f); vy = fmaxf(vy, 0.f); }
        float2 o = make_float2(vx, vy);
        if (which == 0) *(float2*)&g_gat1[node * 64 + tid * 2] = o;
        else            *(float2*)&g_gat2[node * 64 + tid * 2] = o;
    }
}

// -------------------- GRU input matmul (all t), register tiled ------------------
__global__ __launch_bounds__(192)
void gi_kernel(const float* __restrict__ bih0) {
    __shared__ float xsT[64 * 68];
    int t = threadIdx.x;
    int cq = t % 48, rq = t / 48;
    int rowbase = blockIdx.x * 64;

    for (int linear = t; linear < 4096; linear += 192) {
        int r = linear >> 6, k = linear & 63;
        int row = rowbase + r;
        int tt = row / BN, bn = row % BN;
        int b = bn / NN, n = bn % NN;
        xsT[k * 68 + r] = g_gat2[((b * NT + tt) * NN + n) * 64 + k];
    }
    __syncthreads();

    const float4* Wv = (const float4*)g_wih0T;
    float4 acc[16];
#pragma unroll
    for (int i = 0; i < 16; i++) acc[i] = make_float4(0.f, 0.f, 0.f, 0.f);
    int rbase = rq * 16;
    for (int k = 0; k < 64; k++) {
        float4 w = __ldg(&Wv[k * 48 + cq]);
        const float* xk = &xsT[k * 68 + rbase];
#pragma unroll
        for (int i = 0; i < 4; i++) {
            float4 xv = *(const float4*)&xk[i * 4];
            acc[i * 4 + 0].x += xv.x * w.x; acc[i * 4 + 0].y += xv.x * w.y;
            acc[i * 4 + 0].z += xv.x * w.z; acc[i * 4 + 0].w += xv.x * w.w;
            acc[i * 4 + 1].x += xv.y * w.x; acc[i * 4 + 1].y += xv.y * w.y;
            acc[i * 4 + 1].z += xv.y * w.z; acc[i * 4 + 1].w += xv.y * w.w;
            acc[i * 4 + 2].x += xv.z * w.x; acc[i * 4 + 2].y += xv.z * w.y;
            acc[i * 4 + 2].z += xv.z * w.z; acc[i * 4 + 2].w += xv.z * w.w;
            acc[i * 4 + 3].x += xv.w * w.x; acc[i * 4 + 3].y += xv.w * w.y;
            acc[i * 4 + 3].z += xv.w * w.z; acc[i * 4 + 3].w += xv.w * w.w;
        }
    }
    float4 bj = __ldg((const float4*)&bih0[cq * 4]);
#pragma unroll
    for (int i = 0; i < 16; i++) {
        float4 v = acc[i];
        v.x += bj.x; v.y += bj.y; v.z += bj.z; v.w += bj.w;
        *(float4*)&g_gi[(rowbase + rbase + i) * 192 + cq * 4] = v;
    }
}

// -------------------- fused GRU: all 8 steps + head MLP, h-state in smem --------
// 500 blocks x 192 threads; block owns R=8 rows for the entire sequence.
// cq=t%48 (4 cols of 192), rq=t/48 (2 rows each).
__global__ __launch_bounds__(192)
void gru_fused_kernel(const float* __restrict__ bhh0,
                      const float* __restrict__ bih1, const float* __restrict__ bhh1,
                      const float* __restrict__ pW1, const float* __restrict__ pb1,
                      const float* __restrict__ pW2, const float* __restrict__ pb2,
                      float* __restrict__ out) {
    const int R = 8;
    __shared__ float h1T[64 * 10];   // [k][r] padded
    __shared__ float h2T[64 * 10];
    __shared__ float st[R * 196];
    __shared__ float st2[R * 64];

    int tid = threadIdx.x;
    int cq = tid % 48, rq = tid / 48;
    int rowbase = blockIdx.x * R;
    int cbase = cq * 4;
    int gate = cq >> 4;
    int rb = rq * 2;

    for (int idx = tid; idx < 64 * 10; idx += 192) {
        h1T[idx] = 0.f;
        h2T[idx] = 0.f;
    }

    float4 vbhh0 = __ldg((const float4*)&bhh0[cbase]);
    float4 vbih1 = __ldg((const float4*)&bih1[cbase]);
    float4 vbhh1 = __ldg((const float4*)&bhh1[cbase]);

    const float4* W0  = (const float4*)g_whh0T;
    const float4* Wi1 = (const float4*)g_wih1T;
    const float4* Wh1 = (const float4*)g_whh1T;

    for (int t = 0; t < NT; t++) {
        __syncthreads();
        // ---- layer 1: gh = h1 @ Whh0^T ; gi precomputed in g_gi ----
        {
            float4 acc[2];
            acc[0] = make_float4(0.f, 0.f, 0.f, 0.f);
            acc[1] = make_float4(0.f, 0.f, 0.f, 0.f);
            for (int k = 0; k < 64; k++) {
                float4 w = __ldg(&W0[k * 48 + cq]);
                float2 ra = *(const float2*)&h1T[k * 10 + rb];
                acc[0].x += ra.x * w.x; acc[0].y += ra.x * w.y; acc[0].z += ra.x * w.z; acc[0].w += ra.x * w.w;
                acc[1].x += ra.y * w.x; acc[1].y += ra.y * w.y; acc[1].z += ra.y * w.z; acc[1].w += ra.y * w.w;
            }
#pragma unroll
            for (int i = 0; i < 2; i++) {
                int r = rb + i;
                float4 gi = __ldg((const float4*)&g_gi[(t * BN + rowbase + r) * 192 + cbase]);
                float4 gh;
                gh.x = acc[i].x + vbhh0.x; gh.y = acc[i].y + vbhh0.y;
                gh.z = acc[i].z + vbhh0.z; gh.w = acc[i].w + vbhh0.w;
                if (gate < 2) {
                    float4 v = make_float4(gi.x + gh.x, gi.y + gh.y, gi.z + gh.z, gi.w + gh.w);
                    *(float4*)&st[r * 196 + cbase] = v;
                } else {
                    *(float4*)&st[r * 196 + cbase] = gi;
                    *(float4*)&st2[r * 64 + (cbase - 128)] = gh;
                }
            }
        }
        __syncthreads();

        for (int idx = tid; idx < R * 64; idx += 192) {
            int r = idx >> 6, c = idx & 63;
            float rg = fsig(st[r * 196 + c]);
            float zg = fsig(st[r * 196 + 64 + c]);
            float nv = ftanh(st[r * 196 + 128 + c] + rg * st2[r * 64 + c]);
            float h1o = h1T[c * 10 + r];
            h1T[c * 10 + r] = (1.f - zg) * nv + zg * h1o;
        }
        __syncthreads();

        // ---- layer 2: gi = h1n @ Wih1^T ; gh = h2 @ Whh1^T ----
        {
            float4 acci[2], acch[2];
            acci[0] = make_float4(0.f, 0.f, 0.f, 0.f);
            acci[1] = make_float4(0.f, 0.f, 0.f, 0.f);
            acch[0] = make_float4(0.f, 0.f, 0.f, 0.f);
            acch[1] = make_float4(0.f, 0.f, 0.f, 0.f);
            for (int k = 0; k < 64; k++) {
                float4 wi = __ldg(&Wi1[k * 48 + cq]);
                float4 wh = __ldg(&Wh1[k * 48 + cq]);
                float2 a1 = *(const float2*)&h1T[k * 10 + rb];
                float2 a2 = *(const float2*)&h2T[k * 10 + rb];
                acci[0].x += a1.x * wi.x; acci[0].y += a1.x * wi.y; acci[0].z += a1.x * wi.z; acci[0].w += a1.x * wi.w;
                acci[1].x += a1.y * wi.x; acci[1].y += a1.y * wi.y; acci[1].z += a1.y * wi.z; acci[1].w += a1.y * wi.w;
                acch[0].x += a2.x * wh.x; acch[0].y += a2.x * wh.y; acch[0].z += a2.x * wh.z; acch[0].w += a2.x * wh.w;
                acch[1].x += a2.y * wh.x; acch[1].y += a2.y * wh.y; acch[1].z += a2.y * wh.z; acch[1].w += a2.y * wh.w;
            }
#pragma unroll
            for (int i = 0; i < 2; i++) {
                int r = rb + i;
                float4 gi, gh;
                gi.x = acci[i].x + vbih1.x; gi.y = acci[i].y + vbih1.y;
                gi.z = acci[i].z + vbih1.z; gi.w = acci[i].w + vbih1.w;
                gh.x = acch[i].x + vbhh1.x; gh.y = acch[i].y + vbhh1.y;
                gh.z = acch[i].z + vbhh1.z; gh.w = acch[i].w + vbhh1.w;
                if (gate < 2) {
                    float4 v = make_float4(gi.x + gh.x, gi.y + gh.y, gi.z + gh.z, gi.w + gh.w);
                    *(float4*)&st[r * 196 + cbase] = v;
                } else {
                    *(float4*)&st[r * 196 + cbase] = gi;
                    *(float4*)&st2[r * 64 + (cbase - 128)] = gh;
                }
            }
        }
        __syncthreads();

        for (int idx = tid; idx < R * 64; idx += 192) {
            int r = idx >> 6, c = idx & 63;
            float rg = fsig(st[r * 196 + c]);
            float zg = fsig(st[r * 196 + 64 + c]);
            float nv = ftanh(st[r * 196 + 128 + c] + rg * st2[r * 64 + c]);
            float h2o = h2T[c * 10 + r];
            h2T[c * 10 + r] = (1.f - zg) * nv + zg * h2o;
        }
    }
    __syncthreads();

    // ---- head MLP on the 8 rows: mid = relu(h2 @ pW1 + pb1); out = mid @ pW2 + pb2
    if (tid < 64) {
        int j = tid;
#pragma unroll
        for (int r = 0; r < R; r++) {
            float a = __ldg(&pb1[j]);
            for (int k = 0; k < 64; k++) a += h2T[k * 10 + r] * __ldg(&pW1[k * 64 + j]);
            st[r * 68 + j] = fmaxf(a, 0.f);
        }
    }
    __syncthreads();
    if (tid < 80) {
        int r = tid / 10, o = tid % 10;
        float a = __ldg(&pb2[o]);
        for (int k = 0; k < 64; k++) a += st[r * 68 + k] * __ldg(&pW2[k * 10 + o]);
        out[(rowbase + r) * 10 + o] = a;
    }
}

// -------------------- launch ------------------------------------------------------
extern "C" void kernel_launch(void* const* d_in, const int* in_sizes, int n_in,
                              void* d_out, int out_size) {
    const float* x    = (const float*)d_in[0];
    const int*   ei   = (const int*)  d_in[1];
    const float* W1   = (const float*)d_in[3];
    const float* as1  = (const float*)d_in[4];
    const float* ad1  = (const float*)d_in[5];
    const float* b1   = (const float*)d_in[6];
    const float* W2   = (const float*)d_in[7];
    const float* as2  = (const float*)d_in[8];
    const float* ad2  = (const float*)d_in[9];
    const float* b2   = (const float*)d_in[10];
    const float* Wih0 = (const float*)d_in[13];
    const float* Whh0 = (const float*)d_in[14];
    const float* bih0 = (const float*)d_in[15];
    const float* bhh0 = (const float*)d_in[16];
    const float* Wih1 = (const float*)d_in[17];
    const float* Whh1 = (const float*)d_in[18];
    const float* bih1 = (const float*)d_in[19];
    const float* bhh1 = (const float*)d_in[20];
    const float* pW1  = (const float*)d_in[21];
    const float* pb1  = (const float*)d_in[22];
    const float* pW2  = (const float*)d_in[23];
    const float* pb2  = (const float*)d_in[24];
    float* out = (float*)d_out;

    // order matters for ncu sampling: 4th launch (prologue) gets profiled
    init_kernel<<<125, 256>>>();
    hist_kernel<<<500, 256>>>(ei);
    scan_kernel<<<32, 1024>>>();
    prologue_kernel<<<GN / 64, 256>>>(x, W1, as1, ad1, 0);      // 4th: profiled
    scatter_kernel<<<500, 256>>>(ei);
    wtrans_kernel<<<48, 256>>>(Whh0, Wih1, Whh1, Wih0);

    aggregate_kernel<<<GN, 128>>>(b1, 1, 0);
    prologue_kernel<<<GN / 64, 256>>>(nullptr, W2, as2, ad2, 1);
    aggregate_kernel<<<GN, 128>>>(b2, 0, 1);

    gi_kernel<<<(NT * BN) / 64, 192>>>(bih0);
    gru_fused_kernel<<<BN / 8, 192>>>(bhh0, bih1, bhh1, pW1, pb1, pW2, pb2, out);
}

// round 8
// speedup vs baseline: 2.1223x; 1.2250x over previous
#include <cuda_runtime.h>
#include <cuda_fp16.h>
#include <math.h>

#define NB    4
#define NN    1000
#define NT    8
#define NF    64
#define NH    64
#define NHEAD 4
#define NE    16000
#define NG    32
#define GN    32000
#define BN    4000
#define TOTE  512000
#define NEG_SLOPE 0.2f

// -------------------- scratch ------------------------------------------------
__device__ __half2 g_hfeat16[GN * 128];   // h = in @ W, fp16 pairs [node][128]
__device__ float g_asrc[GN * 4];
__device__ float g_adst[GN * 4];
__device__ float g_gat1[GN * 64];
__device__ float g_gat2[GN * 64];
__device__ float g_gi[NT * BN * 192];
__device__ int   g_offs[GN + 1];
__device__ int   g_srclist[TOTE];
// transposed weights [k][j]
__device__ float g_whh0T[64 * 192];
__device__ float g_wih1T[64 * 192];
__device__ float g_whh1T[64 * 192];
__device__ float g_wih0T[64 * 192];

// -------------------- fast math ----------------------------------------------
__device__ __forceinline__ float leaky(float x) { return fmaxf(x, NEG_SLOPE * x); }
__device__ __forceinline__ float fsig(float x) {
    float e = __expf(-fabsf(x));
    float r = __fdividef(1.f, 1.f + e);
    return x >= 0.f ? r : r * e;
}
__device__ __forceinline__ float ftanh(float x) {
    float e = __expf(-2.f * fabsf(x));
    float t = 1.f - __fdividef(2.f * e, 1.f + e);
    return x >= 0.f ? t : -t;
}

// -------------------- weight transpose ------------------------------------------
__global__ void wtrans_kernel(const float* __restrict__ Whh0,
                              const float* __restrict__ Wih1,
                              const float* __restrict__ Whh1,
                              const float* __restrict__ Wih0) {
    int i = blockIdx.x * blockDim.x + threadIdx.x;
    if (i >= 12288) return;
    int j = i / 64, k = i % 64;
    g_whh0T[k * 192 + j] = Whh0[i];
    g_wih1T[k * 192 + j] = Wih1[i];
    g_whh1T[k * 192 + j] = Whh1[i];
    g_wih0T[k * 192 + j] = Wih0[i];
}

// -------------------- fused CSR build: hist + scan + scatter per graph ----------
// 32 blocks x 1024 threads; all counters in smem.
__global__ __launch_bounds__(1024)
void csr_kernel(const int* __restrict__ ei) {
    __shared__ int sdeg[NN];
    __shared__ int wsum[32];
    int g = blockIdx.x;
    int tid = threadIdx.x, lane = tid & 31, wid = tid >> 5;
    const int* srcp = &ei[(g * 2 + 0) * NE];
    const int* dstp = &ei[(g * 2 + 1) * NE];

    if (tid < NN) sdeg[tid] = 0;
    __syncthreads();

    for (int e = tid; e < NE; e += 1024)
        atomicAdd(&sdeg[dstp[e]], 1);
    __syncthreads();

    int d = (tid < NN) ? sdeg[tid] : 0;
    int s = d;
#pragma unroll
    for (int o = 1; o < 32; o <<= 1) {
        int v = __shfl_up_sync(0xffffffffu, s, o);
        if (lane >= o) s += v;
    }
    if (lane == 31) wsum[wid] = s;
    __syncthreads();
    if (wid == 0) {
        int v = wsum[lane];
#pragma unroll
        for (int o = 1; o < 32; o <<= 1) {
            int u = __shfl_up_sync(0xffffffffu, v, o);
            if (lane >= o) v += u;
        }
        wsum[lane] = v;
    }
    __syncthreads();
    int excl = s - d + (wid > 0 ? wsum[wid - 1] : 0);
    __syncthreads();                       // all reads of sdeg done
    if (tid < NN) {
        g_offs[g * NN + tid] = g * NE + excl;
        sdeg[tid] = excl;                  // reuse as cursor (graph-local)
    }
    if (g == 0 && tid == 0) g_offs[GN] = TOTE;
    __syncthreads();

    int base = g * NE;
    for (int e = tid; e < NE; e += 1024) {
        int src = srcp[e];
        int pos = atomicAdd(&sdeg[dstp[e]], 1);
        g_srclist[base + pos] = src;
    }
}

// -------------------- GAT prologue + attention scalars -------------------------
// 32 nodes/block, 256 threads: cq = t&63 -> 4 cols, rq = t>>6 -> 8 rows.
__global__ __launch_bounds__(256)
void prologue_kernel(const float* __restrict__ in, const float* __restrict__ W,
                     const float* __restrict__ att_src, const float* __restrict__ att_dst,
                     int mode) {
    __shared__ float xsT[64 * 36];   // [k][r], 32 rows padded to 36
    int t = threadIdx.x;
    int cq = t & 63, rq = t >> 6;
    int lane = t & 31;
    int nodebase = blockIdx.x * 32;

    for (int linear = t; linear < 2048; linear += 256) {
        int r = linear >> 6, k = linear & 63;
        int node = nodebase + r;
        float v;
        if (mode == 0) {
            int gg = node / NN, n = node % NN;
            int b = gg >> 3, tt = gg & 7;
            v = in[((b * NN + n) * NT + tt) * NF + k];
        } else {
            v = g_gat1[node * 64 + k];
        }
        xsT[k * 36 + r] = v;
    }
    __syncthreads();

    const float4* Wv = (const float4*)W;
    float4 acc[8];
#pragma unroll
    for (int i = 0; i < 8; i++) acc[i] = make_float4(0.f, 0.f, 0.f, 0.f);

    int rbase = rq * 8;
    for (int k = 0; k < 64; k++) {
        float4 w = __ldg(&Wv[k * 64 + cq]);
        const float* xk = &xsT[k * 36 + rbase];
#pragma unroll
        for (int i = 0; i < 2; i++) {
            float4 xv = *(const float4*)&xk[i * 4];
            acc[i * 4 + 0].x += xv.x * w.x; acc[i * 4 + 0].y += xv.x * w.y;
            acc[i * 4 + 0].z += xv.x * w.z; acc[i * 4 + 0].w += xv.x * w.w;
            acc[i * 4 + 1].x += xv.y * w.x; acc[i * 4 + 1].y += xv.y * w.y;
            acc[i * 4 + 1].z += xv.y * w.z; acc[i * 4 + 1].w += xv.y * w.w;
            acc[i * 4 + 2].x += xv.z * w.x; acc[i * 4 + 2].y += xv.z * w.y;
            acc[i * 4 + 2].z += xv.z * w.z; acc[i * 4 + 2].w += xv.z * w.w;
            acc[i * 4 + 3].x += xv.w * w.x; acc[i * 4 + 3].y += xv.w * w.y;
            acc[i * 4 + 3].z += xv.w * w.z; acc[i * 4 + 3].w += xv.w * w.w;
        }
    }

    float4 as4 = __ldg((const float4*)&att_src[cq * 4]);
    float4 ad4 = __ldg((const float4*)&att_dst[cq * 4]);
    int hd = cq >> 4;

#pragma unroll
    for (int i = 0; i < 8; i++) {
        int node = nodebase + rbase + i;
        float4 a = acc[i];

        __half2 h0 = __floats2half2_rn(a.x, a.y);
        __half2 h1 = __floats2half2_rn(a.z, a.w);
        uint2 u;
        u.x = *(unsigned*)&h0;
        u.y = *(unsigned*)&h1;
        *(uint2*)&g_hfeat16[node * 128 + cq * 2] = u;

        float ps = a.x * as4.x + a.y * as4.y + a.z * as4.z + a.w * as4.w;
        float pd = a.x * ad4.x + a.y * ad4.y + a.z * ad4.z + a.w * ad4.w;
#pragma unroll
        for (int o = 8; o; o >>= 1) {
            ps += __shfl_xor_sync(0xffffffffu, ps, o);
            pd += __shfl_xor_sync(0xffffffffu, pd, o);
        }
        if ((lane & 15) == 0) {
            g_asrc[node * 4 + hd] = ps;
            g_adst[node * 4 + hd] = pd;
        }
    }
}

// -------------------- GAT aggregation: one warp per node -------------------------
// lane roles: weight phase (eh_e = lane>>2 edge slot, eh_h = lane&3 head);
// feature phase (lane covers channels 8*lane .. 8*lane+7, head = lane>>3).
__global__ __launch_bounds__(256)
void aggregate_kernel(const float* __restrict__ bias, int relu_flag, int which) {
    int node = blockIdx.x * 8 + (threadIdx.x >> 5);
    int lane = threadIdx.x & 31;
    int g = node / NN;
    int gbase = g * NN;
    int off = g_offs[node];
    int deg = g_offs[node + 1] - off;

    int eh_e = lane >> 2, eh_h = lane & 3;
    int fh = lane >> 3;                      // feature head

    float4 ad4 = *(const float4*)&g_adst[node * 4];
    float4 asn = *(const float4*)&g_asrc[node * 4];
    float adh_w = ((const float*)&ad4)[eh_h];
    float w_self = __expf(leaky(((const float*)&asn)[fh] + ((const float*)&ad4)[fh]));

    float acc[8];
    {
        uint4 raw = *(const uint4*)&g_hfeat16[node * 128 + lane * 4];
        const __half2* hp = (const __half2*)&raw;
        float2 f0 = __half22float2(hp[0]), f1 = __half22float2(hp[1]);
        float2 f2 = __half22float2(hp[2]), f3 = __half22float2(hp[3]);
        acc[0] = w_self * f0.x; acc[1] = w_self * f0.y;
        acc[2] = w_self * f1.x; acc[3] = w_self * f1.y;
        acc[4] = w_self * f2.x; acc[5] = w_self * f2.y;
        acc[6] = w_self * f3.x; acc[7] = w_self * f3.y;
    }

    float s_part = 0.f;
    for (int base = 0; base < deg; base += 8) {
        int rem = deg - base;
        bool valid = eh_e < rem;
        int src = g_srclist[off + base + (valid ? eh_e : 0)];
        int sg = gbase + src;
        float w = 0.f;
        if (valid) w = __expf(leaky(__ldg(&g_asrc[sg * 4 + eh_h]) + adh_w));
        s_part += w;
        int cnt = min(8, rem);
        for (int j = 0; j < cnt; j++) {
            int sj = __shfl_sync(0xffffffffu, sg, j * 4);
            float wj = __shfl_sync(0xffffffffu, w, j * 4 + fh);
            uint4 raw = __ldg((const uint4*)&g_hfeat16[sj * 128 + lane * 4]);
            const __half2* hp = (const __half2*)&raw;
            float2 f0 = __half22float2(hp[0]), f1 = __half22float2(hp[1]);
            float2 f2 = __half22float2(hp[2]), f3 = __half22float2(hp[3]);
            acc[0] += wj * f0.x; acc[1] += wj * f0.y;
            acc[2] += wj * f1.x; acc[3] += wj * f1.y;
            acc[4] += wj * f2.x; acc[5] += wj * f2.y;
            acc[6] += wj * f3.x; acc[7] += wj * f3.y;
        }
    }

    // sum s over edge-slot lanes (same eh_h): xor over bits 2,3,4
    s_part += __shfl_xor_sync(0xffffffffu, s_part, 4);
    s_part += __shfl_xor_sync(0xffffffffu, s_part, 8);
    s_part += __shfl_xor_sync(0xffffffffu, s_part, 16);
    // lane 'fh' (0..3) holds s for head fh (its eh_h == fh)
    float s_tot = __shfl_sync(0xffffffffu, s_part, fh) + w_self;
    float inv = __fdividef(1.f, s_tot);
#pragma unroll
    for (int i = 0; i < 8; i++) acc[i] *= inv;

    // mean over heads: channels repeat with lane period 8 (head = lane>>3)
#pragma unroll
    for (int i = 0; i < 8; i++) {
        acc[i] += __shfl_xor_sync(0xffffffffu, acc[i], 8);
        acc[i] += __shfl_xor_sync(0xffffffffu, acc[i], 16);
    }

    if (lane < 8) {
        float4 b0 = __ldg((const float4*)&bias[lane * 8]);
        float4 b1 = __ldg((const float4*)&bias[lane * 8 + 4]);
        float4 o0, o1;
        o0.x = acc[0] * 0.25f + b0.x; o0.y = acc[1] * 0.25f + b0.y;
        o0.z = acc[2] * 0.25f + b0.z; o0.w = acc[3] * 0.25f + b0.w;
        o1.x = acc[4] * 0.25f + b1.x; o1.y = acc[5] * 0.25f + b1.y;
        o1.z = acc[6] * 0.25f + b1.z; o1.w = acc[7] * 0.25f + b1.w;
        if (relu_flag) {
            o0.x = fmaxf(o0.x, 0.f); o0.y = fmaxf(o0.y, 0.f);
            o0.z = fmaxf(o0.z, 0.f); o0.w = fmaxf(o0.w, 0.f);
            o1.x = fmaxf(o1.x, 0.f); o1.y = fmaxf(o1.y, 0.f);
            o1.z = fmaxf(o1.z, 0.f); o1.w = fmaxf(o1.w, 0.f);
        }
        float* dst = (which == 0) ? g_gat1 : g_gat2;
        *(float4*)&dst[node * 64 + lane * 8] = o0;
        *(float4*)&dst[node * 64 + lane * 8 + 4] = o1;
    }
}

// -------------------- GRU input matmul (all t), register tiled ------------------
__global__ __launch_bounds__(192)
void gi_kernel(const float* __restrict__ bih0) {
    __shared__ float xsT[64 * 68];
    int t = threadIdx.x;
    int cq = t % 48, rq = t / 48;
    int rowbase = blockIdx.x * 64;

    for (int linear = t; linear < 4096; linear += 192) {
        int r = linear >> 6, k = linear & 63;
        int row = rowbase + r;
        int tt = row / BN, bn = row % BN;
        int b = bn / NN, n = bn % NN;
        xsT[k * 68 + r] = g_gat2[((b * NT + tt) * NN + n) * 64 + k];
    }
    __syncthreads();

    const float4* Wv = (const float4*)g_wih0T;
    float4 acc[16];
#pragma unroll
    for (int i = 0; i < 16; i++) acc[i] = make_float4(0.f, 0.f, 0.f, 0.f);
    int rbase = rq * 16;
    for (int k = 0; k < 64; k++) {
        float4 w = __ldg(&Wv[k * 48 + cq]);
        const float* xk = &xsT[k * 68 + rbase];
#pragma unroll
        for (int i = 0; i < 4; i++) {
            float4 xv = *(const float4*)&xk[i * 4];
            acc[i * 4 + 0].x += xv.x * w.x; acc[i * 4 + 0].y += xv.x * w.y;
            acc[i * 4 + 0].z += xv.x * w.z; acc[i * 4 + 0].w += xv.x * w.w;
            acc[i * 4 + 1].x += xv.y * w.x; acc[i * 4 + 1].y += xv.y * w.y;
            acc[i * 4 + 1].z += xv.y * w.z; acc[i * 4 + 1].w += xv.y * w.w;
            acc[i * 4 + 2].x += xv.z * w.x; acc[i * 4 + 2].y += xv.z * w.y;
            acc[i * 4 + 2].z += xv.z * w.z; acc[i * 4 + 2].w += xv.z * w.w;
            acc[i * 4 + 3].x += xv.w * w.x; acc[i * 4 + 3].y += xv.w * w.y;
            acc[i * 4 + 3].z += xv.w * w.z; acc[i * 4 + 3].w += xv.w * w.w;
        }
    }
    float4 bj = __ldg((const float4*)&bih0[cq * 4]);
#pragma unroll
    for (int i = 0; i < 16; i++) {
        float4 v = acc[i];
        v.x += bj.x; v.y += bj.y; v.z += bj.z; v.w += bj.w;
        *(float4*)&g_gi[(rowbase + rbase + i) * 192 + cq * 4] = v;
    }
}

// -------------------- fused GRU: all 8 steps + head MLP, h-state in smem --------
__global__ __launch_bounds__(192)
void gru_fused_kernel(const float* __restrict__ bhh0,
                      const float* __restrict__ bih1, const float* __restrict__ bhh1,
                      const float* __restrict__ pW1, const float* __restrict__ pb1,
                      const float* __restrict__ pW2, const float* __restrict__ pb2,
                      float* __restrict__ out) {
    const int R = 8;
    __shared__ float h1T[64 * 10];
    __shared__ float h2T[64 * 10];
    __shared__ float st[R * 196];
    __shared__ float st2[R * 64];

    int tid = threadIdx.x;
    int cq = tid % 48, rq = tid / 48;
    int rowbase = blockIdx.x * R;
    int cbase = cq * 4;
    int gate = cq >> 4;
    int rb = rq * 2;

    for (int idx = tid; idx < 64 * 10; idx += 192) {
        h1T[idx] = 0.f;
        h2T[idx] = 0.f;
    }

    float4 vbhh0 = __ldg((const float4*)&bhh0[cbase]);
    float4 vbih1 = __ldg((const float4*)&bih1[cbase]);
    float4 vbhh1 = __ldg((const float4*)&bhh1[cbase]);

    const float4* W0  = (const float4*)g_whh0T;
    const float4* Wi1 = (const float4*)g_wih1T;
    const float4* Wh1 = (const float4*)g_whh1T;

    for (int t = 0; t < NT; t++) {
        __syncthreads();
        {
            float4 acc[2];
            acc[0] = make_float4(0.f, 0.f, 0.f, 0.f);
            acc[1] = make_float4(0.f, 0.f, 0.f, 0.f);
            for (int k = 0; k < 64; k++) {
                float4 w = __ldg(&W0[k * 48 + cq]);
                float2 ra = *(const float2*)&h1T[k * 10 + rb];
                acc[0].x += ra.x * w.x; acc[0].y += ra.x * w.y; acc[0].z += ra.x * w.z; acc[0].w += ra.x * w.w;
                acc[1].x += ra.y * w.x; acc[1].y += ra.y * w.y; acc[1].z += ra.y * w.z; acc[1].w += ra.y * w.w;
            }
#pragma unroll
            for (int i = 0; i < 2; i++) {
                int r = rb + i;
                float4 gi = __ldg((const float4*)&g_gi[(t * BN + rowbase + r) * 192 + cbase]);
                float4 gh;
                gh.x = acc[i].x + vbhh0.x; gh.y = acc[i].y + vbhh0.y;
                gh.z = acc[i].z + vbhh0.z; gh.w = acc[i].w + vbhh0.w;
                if (gate < 2) {
                    float4 v = make_float4(gi.x + gh.x, gi.y + gh.y, gi.z + gh.z, gi.w + gh.w);
                    *(float4*)&st[r * 196 + cbase] = v;
                } else {
                    *(float4*)&st[r * 196 + cbase] = gi;
                    *(float4*)&st2[r * 64 + (cbase - 128)] = gh;
                }
            }
        }
        __syncthreads();

        for (int idx = tid; idx < R * 64; idx += 192) {
            int r = idx >> 6, c = idx & 63;
            float rg = fsig(st[r * 196 + c]);
            float zg = fsig(st[r * 196 + 64 + c]);
            float nv = ftanh(st[r * 196 + 128 + c] + rg * st2[r * 64 + c]);
            float h1o = h1T[c * 10 + r];
            h1T[c * 10 + r] = (1.f - zg) * nv + zg * h1o;
        }
        __syncthreads();

        {
            float4 acci[2], acch[2];
            acci[0] = make_float4(0.f, 0.f, 0.f, 0.f);
            acci[1] = make_float4(0.f, 0.f, 0.f, 0.f);
            acch[0] = make_float4(0.f, 0.f, 0.f, 0.f);
            acch[1] = make_float4(0.f, 0.f, 0.f, 0.f);
            for (int k = 0; k < 64; k++) {
                float4 wi = __ldg(&Wi1[k * 48 + cq]);
                float4 wh = __ldg(&Wh1[k * 48 + cq]);
                float2 a1 = *(const float2*)&h1T[k * 10 + rb];
                float2 a2 = *(const float2*)&h2T[k * 10 + rb];
                acci[0].x += a1.x * wi.x; acci[0].y += a1.x * wi.y; acci[0].z += a1.x * wi.z; acci[0].w += a1.x * wi.w;
                acci[1].x += a1.y * wi.x; acci[1].y += a1.y * wi.y; acci[1].z += a1.y * wi.z; acci[1].w += a1.y * wi.w;
                acch[0].x += a2.x * wh.x; acch[0].y += a2.x * wh.y; acch[0].z += a2.x * wh.z; acch[0].w += a2.x * wh.w;
                acch[1].x += a2.y * wh.x; acch[1].y += a2.y * wh.y; acch[1].z += a2.y * wh.z; acch[1].w += a2.y * wh.w;
            }
#pragma unroll
            for (int i = 0; i < 2; i++) {
                int r = rb + i;
                float4 gi, gh;
                gi.x = acci[i].x + vbih1.x; gi.y = acci[i].y + vbih1.y;
                gi.z = acci[i].z + vbih1.z; gi.w = acci[i].w + vbih1.w;
                gh.x = acch[i].x + vbhh1.x; gh.y = acch[i].y + vbhh1.y;
                gh.z = acch[i].z + vbhh1.z; gh.w = acch[i].w + vbhh1.w;
                if (gate < 2) {
                    float4 v = make_float4(gi.x + gh.x, gi.y + gh.y, gi.z + gh.z, gi.w + gh.w);
                    *(float4*)&st[r * 196 + cbase] = v;
                } else {
                    *(float4*)&st[r * 196 + cbase] = gi;
                    *(float4*)&st2[r * 64 + (cbase - 128)] = gh;
                }
            }
        }
        __syncthreads();

        for (int idx = tid; idx < R * 64; idx += 192) {
            int r = idx >> 6, c = idx & 63;
            float rg = fsig(st[r * 196 + c]);
            float zg = fsig(st[r * 196 + 64 + c]);
            float nv = ftanh(st[r * 196 + 128 + c] + rg * st2[r * 64 + c]);
            float h2o = h2T[c * 10 + r];
            h2T[c * 10 + r] = (1.f - zg) * nv + zg * h2o;
        }
    }
    __syncthreads();

    if (tid < 64) {
        int j = tid;
#pragma unroll
        for (int r = 0; r < R; r++) {
            float a = __ldg(&pb1[j]);
            for (int k = 0; k < 64; k++) a += h2T[k * 10 + r] * __ldg(&pW1[k * 64 + j]);
            st[r * 68 + j] = fmaxf(a, 0.f);
        }
    }
    __syncthreads();
    if (tid < 80) {
        int r = tid / 10, o = tid % 10;
        float a = __ldg(&pb2[o]);
        for (int k = 0; k < 64; k++) a += st[r * 68 + k] * __ldg(&pW2[k * 10 + o]);
        out[(rowbase + r) * 10 + o] = a;
    }
}

// -------------------- launch ------------------------------------------------------
extern "C" void kernel_launch(void* const* d_in, const int* in_sizes, int n_in,
                              void* d_out, int out_size) {
    const float* x    = (const float*)d_in[0];
    const int*   ei   = (const int*)  d_in[1];
    const float* W1   = (const float*)d_in[3];
    const float* as1  = (const float*)d_in[4];
    const float* ad1  = (const float*)d_in[5];
    const float* b1   = (const float*)d_in[6];
    const float* W2   = (const float*)d_in[7];
    const float* as2  = (const float*)d_in[8];
    const float* ad2  = (const float*)d_in[9];
    const float* b2   = (const float*)d_in[10];
    const float* Wih0 = (const float*)d_in[13];
    const float* Whh0 = (const float*)d_in[14];
    const float* bih0 = (const float*)d_in[15];
    const float* bhh0 = (const float*)d_in[16];
    const float* Wih1 = (const float*)d_in[17];
    const float* Whh1 = (const float*)d_in[18];
    const float* bih1 = (const float*)d_in[19];
    const float* bhh1 = (const float*)d_in[20];
    const float* pW1  = (const float*)d_in[21];
    const float* pb1  = (const float*)d_in[22];
    const float* pW2  = (const float*)d_in[23];
    const float* pb2  = (const float*)d_in[24];
    float* out = (float*)d_out;

    csr_kernel<<<NG, 1024>>>(ei);                              // 1
    wtrans_kernel<<<48, 256>>>(Whh0, Wih1, Whh1, Wih0);        // 2
    prologue_kernel<<<GN / 32, 256>>>(x, W1, as1, ad1, 0);     // 3
    aggregate_kernel<<<GN / 8, 256>>>(b1, 1, 0);               // 4 <- profiled
    prologue_kernel<<<GN / 32, 256>>>(nullptr, W2, as2, ad2, 1); // 5
    aggregate_kernel<<<GN / 8, 256>>>(b2, 0, 1);               // 6
    gi_kernel<<<(NT * BN) / 64, 192>>>(bih0);                  // 7
    gru_fused_kernel<<<BN / 8, 192>>>(bhh0, bih1, bhh1, pW1, pb1, pW2, pb2, out); // 8
}